// round 9
// baseline (speedup 1.0000x reference)
#include <cuda_runtime.h>
#include <cstdint>
#include <cstddef>

#define NN 3072
#define FB 512     // working block width (256 complex -> 512 real cols, interleaved RIRI)
#define FOUT 256
#define FIN 512
#define NPACK 1280 // [wr1|wi1 | wr0|wi0 | w0]

// ---------------- scratch (device globals) -------------------------------------
__device__ __align__(1024) uint32_t g_adjp[(size_t)NN * NN / 2]; // bf16 fragment-tiled adj
__device__ __align__(1024) uint32_t g_Bbf0[(NN / 2) * FB];       // bf16x2 B operand (ping)
__device__ __align__(1024) uint32_t g_Bbf1[(NN / 2) * FB];       // bf16x2 B operand (pong)
__device__ __align__(1024) uint32_t g_xh[(size_t)NN * FIN / 2];  // x fragment-tiled bf16 hi
__device__ __align__(1024) uint32_t g_xl[(size_t)NN * FIN / 2];  // x fragment-tiled bf16 lo
__device__ __align__(1024) uint32_t g_wh[(FIN / 2) * NPACK];     // WALL pair-rows bf16 hi
__device__ __align__(1024) uint32_t g_wl[(FIN / 2) * NPACK];     // WALL pair-rows bf16 lo
__device__ __align__(128) float g_P[NN * NPACK];                 // packed projections (fp32)
__device__ __align__(128) float g_WALL[FIN * NPACK];
__device__ __align__(128) float g_Q[NN * FB];                    // interleaved RIRI
__device__ __align__(128) float g_Y[NN * FB];                    // interleaved RIRI
__device__ __align__(128) float g_XJ[NN * FB];                   // interleaved RIRI
__device__ __align__(128) float g_G[3 * NN * FB];                // split-K partials
__device__ __align__(128) float g_dr[NN];
__device__ __align__(128) float g_di[NN];
__device__ int g_cnt[96];                                        // per-tile arrival counters

// ---------------- helpers -------------------------------------------------------
__device__ __forceinline__ uint32_t packbf(float lo, float hi) {
    uint32_t d;
    asm("cvt.rn.bf16x2.f32 %0, %1, %2;" : "=r"(d) : "f"(hi), "f"(lo));
    return d;
}
__device__ __forceinline__ uint32_t packres(float lo, float hi, uint32_t h) {
    const float hl = __uint_as_float(h << 16);
    const float hh = __uint_as_float(h & 0xFFFF0000u);
    return packbf(lo - hl, hi - hh);
}
__device__ __forceinline__ uint32_t smem_u32(const void* p) {
    uint32_t a;
    asm("{ .reg .u64 t; cvta.to.shared.u64 t, %1; cvt.u32.u64 %0, t; }" : "=r"(a) : "l"(p));
    return a;
}
__device__ __forceinline__ void cpasync16(uint32_t dst, const void* src) {
    asm volatile("cp.async.cg.shared.global [%0], [%1], 16;" :: "r"(dst), "l"(src) : "memory");
}
__device__ __forceinline__ void mma16(float c[4],
                                      uint32_t a0, uint32_t a1, uint32_t a2, uint32_t a3,
                                      uint32_t b0, uint32_t b1) {
    asm volatile(
        "mma.sync.aligned.m16n8k16.row.col.f32.bf16.bf16.f32 "
        "{%0,%1,%2,%3}, {%4,%5,%6,%7}, {%8,%9}, {%0,%1,%2,%3};"
        : "+f"(c[0]), "+f"(c[1]), "+f"(c[2]), "+f"(c[3])
        : "r"(a0), "r"(a1), "r"(a2), "r"(a3), "r"(b0), "r"(b1));
}

// ================= FUSED BIG GEMM + split-K reduce + xj/jacobi epilogue ==========
// Mainloop: G_partial[z] = adj[:, zslice] @ Ybf[zslice, :]  (128x128 CTA, cp.async x3)
// Epilogue (last CTA per tile): sum 3 partials (deterministic order), apply xj or
// jacobi pointwise update on interleaved complex cols, write Y/XJ fp32 and next
// B operand (bf16x2 row-pairs) via shfl.
#define EPI_XJ  0
#define EPI_JAC 1

template <int EPI>
__global__ void __launch_bounds__(256, 2)
gemm_fused(const uint32_t* __restrict__ Ap, const uint32_t* __restrict__ Bin,
           float* __restrict__ G, int* __restrict__ cnt,
           const float* __restrict__ hp,
           const float* __restrict__ drv, const float* __restrict__ dis,
           uint32_t* __restrict__ Bout,
           float* __restrict__ XJ, float* __restrict__ Y,
           const float* __restrict__ Qsrc) {
    constexpr int STAGE = 4288;    // u32: A 2112 + B 16*136
    extern __shared__ __align__(16) uint32_t sm[];
    const uint32_t smb = smem_u32(sm);

    const int tid  = threadIdx.x;
    const int lane = tid & 31;
    const int warp = tid >> 5;
    const int wrow = warp >> 2;
    const int wcol = warp & 3;
    const int g    = lane >> 2;
    const int t    = lane & 3;
    const int bMt  = blockIdx.y;
    const int bN   = blockIdx.x * 128;
    const int kt0  = blockIdx.z * 64;

    float acc[4][4][4];
#pragma unroll
    for (int i = 0; i < 4; i++)
#pragma unroll
        for (int j = 0; j < 4; j++)
#pragma unroll
            for (int k = 0; k < 4; k++) acc[i][j][k] = 0.f;

    auto issueStage = [&](int st, int s) {
        const uint32_t stb = smb + st * (STAGE * 4);
        const int kt16 = kt0 + s * 2;
        const size_t atile = ((size_t)bMt * 192 + kt16) * 1024;
#pragma unroll
        for (int i = 0; i < 2; i++) {
            const int c = tid + i * 256;
            const int j = c >> 8, w = c & 255;
            cpasync16(stb + (uint32_t)(j * 1056 + (w >> 6) * 264 + (w & 63) * 4) * 4,
                      Ap + atile + c * 4);
        }
        const size_t brow = (size_t)kt16 * 8 * FB + bN;
#pragma unroll
        for (int i = 0; i < 2; i++) {
            const int c = tid + i * 256;
            const int row = c >> 5, c4 = (c & 31) * 4;
            cpasync16(stb + 8448 + (uint32_t)(row * 136 + c4) * 4,
                      Bin + brow + (size_t)row * FB + c4);
        }
        asm volatile("cp.async.commit_group;" ::: "memory");
    };

    const int nT = 32;
    issueStage(0, 0);
    issueStage(1, 1);

    for (int s = 0; s < nT; s++) {
        const int st = s % 3;
        if (s + 1 < nT) asm volatile("cp.async.wait_group 1;" ::: "memory");
        else            asm volatile("cp.async.wait_group 0;" ::: "memory");
        __syncthreads();
        if (s + 2 < nT) issueStage((s + 2) % 3, s + 2);

        const uint32_t* Abase = sm + st * STAGE + t * 264;
        const uint32_t* Bbase = sm + st * STAGE + 2112;
#pragma unroll
        for (int ks = 0; ks < 2; ks++) {
            uint4 afv[4];
            uint32_t bf[4][2];
#pragma unroll
            for (int mti = 0; mti < 4; mti++)
                afv[mti] = *(const uint4*)(Abase + ks * 1056 + ((wrow * 4 + mti) * 8 + g) * 4);
#pragma unroll
            for (int nt = 0; nt < 4; nt++) {
                const int n0 = wcol * 32 + nt * 8 + g;
                bf[nt][0] = Bbase[(ks * 8 + t) * 136 + n0];
                bf[nt][1] = Bbase[(ks * 8 + t + 4) * 136 + n0];
            }
#pragma unroll
            for (int mti = 0; mti < 4; mti++)
#pragma unroll
                for (int nt = 0; nt < 4; nt++)
                    mma16(acc[mti][nt], afv[mti].x, afv[mti].y, afv[mti].z, afv[mti].w,
                          bf[nt][0], bf[nt][1]);
        }
        __syncthreads();
    }

    // ---- store partials (plane z) ----
    const size_t PL = (size_t)NN * FB;
    float* Gz = G + blockIdx.z * PL;
#pragma unroll
    for (int mti = 0; mti < 4; mti++) {
        const int row = bMt * 128 + wrow * 64 + mti * 16 + g;
#pragma unroll
        for (int nt = 0; nt < 4; nt++) {
            const int col = bN + wcol * 32 + nt * 8 + 2 * t;
            float* p = Gz + (size_t)row * FB + col;
            *(float2*)p = make_float2(acc[mti][nt][0], acc[mti][nt][1]);
            *(float2*)(p + 8 * FB) = make_float2(acc[mti][nt][2], acc[mti][nt][3]);
        }
    }
    __threadfence();
    __syncthreads();
    __shared__ int lastFlag;
    const int tileId = blockIdx.y * 4 + blockIdx.x;
    if (tid == 0) lastFlag = (atomicAdd(&cnt[tileId], 1) == 2);
    __syncthreads();
    if (!lastFlag) return;
    if (tid == 0) cnt[tileId] = 0;
    __threadfence();

    // ---- last CTA: reduce + elementwise + pack next B operand ----
    const float h = *hp;
    const int z = blockIdx.z;
#pragma unroll
    for (int mti = 0; mti < 4; mti++) {
        const int row0 = bMt * 128 + wrow * 64 + mti * 16 + g;
        const int row1 = row0 + 8;
#pragma unroll
        for (int nt = 0; nt < 4; nt++) {
            const int col = bN + wcol * 32 + nt * 8 + 2 * t;
            float s0r = 0.f, s0i = 0.f, s1r = 0.f, s1i = 0.f;
#pragma unroll
            for (int j = 0; j < 3; j++) {       // deterministic order 0,1,2
                if (j == z) {
                    s0r += acc[mti][nt][0]; s0i += acc[mti][nt][1];
                    s1r += acc[mti][nt][2]; s1i += acc[mti][nt][3];
                } else {
                    const float* Gp = G + (size_t)j * PL;
                    const float2 v0 = *(const float2*)(Gp + (size_t)row0 * FB + col);
                    const float2 v1 = *(const float2*)(Gp + (size_t)row1 * FB + col);
                    s0r += v0.x; s0i += v0.y; s1r += v1.x; s1i += v1.y;
                }
            }
            float y0r, y0i, y1r, y1i;
            if (EPI == EPI_XJ) {
                const float2 q0 = *(const float2*)(Qsrc + (size_t)row0 * FB + col);
                const float2 q1 = *(const float2*)(Qsrc + (size_t)row1 * FB + col);
                y0r = h * q0.x - h * s0r + q0.y;
                y0i = h * q0.y - h * s0i - q0.x;
                y1r = h * q1.x - h * s1r + q1.y;
                y1i = h * q1.y - h * s1i - q1.x;
                *(float2*)(XJ + (size_t)row0 * FB + col) = make_float2(y0r, y0i);
                *(float2*)(XJ + (size_t)row1 * FB + col) = make_float2(y1r, y1i);
            } else {
                const float2 yv0 = *(const float2*)(Y + (size_t)row0 * FB + col);
                const float2 yv1 = *(const float2*)(Y + (size_t)row1 * FB + col);
                const float2 x0 = *(const float2*)(XJ + (size_t)row0 * FB + col);
                const float2 x1 = *(const float2*)(XJ + (size_t)row1 * FB + col);
                const float r0r = x0.x - (h * yv0.x - h * s0r - yv0.y);
                const float r0i = x0.y - (h * yv0.y - h * s0i + yv0.x);
                const float r1r = x1.x - (h * yv1.x - h * s1r - yv1.y);
                const float r1i = x1.y - (h * yv1.y - h * s1i + yv1.x);
                const float d0r = drv[row0], d0i = dis[row0];
                const float d1r = drv[row1], d1i = dis[row1];
                y0r = yv0.x + d0r * r0r - d0i * r0i;
                y0i = yv0.y + d0r * r0i + d0i * r0r;
                y1r = yv1.x + d1r * r1r - d1i * r1i;
                y1i = yv1.y + d1r * r1i + d1i * r1r;
            }
            *(float2*)(Y + (size_t)row0 * FB + col) = make_float2(y0r, y0i);
            *(float2*)(Y + (size_t)row1 * FB + col) = make_float2(y1r, y1i);
            // pack next B operand: row pairs (2r, 2r+1) via shfl across g^1
            const float p0r = __shfl_xor_sync(0xffffffffu, y0r, 4);
            const float p0i = __shfl_xor_sync(0xffffffffu, y0i, 4);
            const float p1r = __shfl_xor_sync(0xffffffffu, y1r, 4);
            const float p1i = __shfl_xor_sync(0xffffffffu, y1i, 4);
            if (!(g & 1)) {
                *(uint2*)(Bout + (size_t)(row0 >> 1) * FB + col) =
                    make_uint2(packbf(y0r, p0r), packbf(y0i, p0i));
                *(uint2*)(Bout + (size_t)(row1 >> 1) * FB + col) =
                    make_uint2(packbf(y1r, p1r), packbf(y1i, p1i));
            }
        }
    }
}

// ================= projection GEMM (split-bf16 pipelined), unchanged =============
template <bool SPLIT>
__global__ void __launch_bounds__(256, 2)
gemm_pipe(const uint32_t* __restrict__ Ah, const uint32_t* __restrict__ Al,
          const uint32_t* __restrict__ Bh, const uint32_t* __restrict__ Bl,
          float* __restrict__ C, int ldc, int ldb, int aTiles,
          int nStages, size_t cPlane) {
    constexpr int AU = 2112;
    constexpr int BOFF = SPLIT ? 4224 : 2112;
    constexpr int BU = 16 * 136;
    constexpr int STAGE = BOFF + (SPLIT ? 2 : 1) * BU;

    extern __shared__ __align__(16) uint32_t sm[];
    const uint32_t smb = smem_u32(sm);

    const int tid  = threadIdx.x;
    const int lane = tid & 31;
    const int warp = tid >> 5;
    const int wrow = warp >> 2;
    const int wcol = warp & 3;
    const int g    = lane >> 2;
    const int t    = lane & 3;
    const int bMt  = blockIdx.y;
    const int bN   = blockIdx.x * 128;
    const int kt0  = blockIdx.z * (nStages * 2);

    float acc[4][4][4];
#pragma unroll
    for (int i = 0; i < 4; i++)
#pragma unroll
        for (int j = 0; j < 4; j++)
#pragma unroll
            for (int k = 0; k < 4; k++) acc[i][j][k] = 0.f;

    auto issueStage = [&](int st, int s) {
        const uint32_t stb = smb + st * (STAGE * 4);
        const int kt16 = kt0 + s * 2;
        const size_t atile = ((size_t)bMt * aTiles + kt16) * 1024;
#pragma unroll
        for (int i = 0; i < 2; i++) {
            const int c = tid + i * 256;
            const int j = c >> 8, w = c & 255;
            const uint32_t off = (uint32_t)(j * 1056 + (w >> 6) * 264 + (w & 63) * 4) * 4;
            cpasync16(stb + off, Ah + atile + c * 4);
            if (SPLIT) cpasync16(stb + AU * 4 + off, Al + atile + c * 4);
        }
        const size_t brow = (size_t)kt16 * 8 * ldb + bN;
#pragma unroll
        for (int i = 0; i < 2; i++) {
            const int c = tid + i * 256;
            const int row = c >> 5, c4 = (c & 31) * 4;
            const uint32_t off = (uint32_t)(row * 136 + c4) * 4;
            cpasync16(stb + BOFF * 4 + off, Bh + brow + (size_t)row * ldb + c4);
            if (SPLIT) cpasync16(stb + (BOFF + BU) * 4 + off,
                                 Bl + brow + (size_t)row * ldb + c4);
        }
        asm volatile("cp.async.commit_group;" ::: "memory");
    };

    issueStage(0, 0);
    issueStage(1, 1);

    for (int s = 0; s < nStages; s++) {
        const int st = s % 3;
        if (s + 1 < nStages) asm volatile("cp.async.wait_group 1;" ::: "memory");
        else                 asm volatile("cp.async.wait_group 0;" ::: "memory");
        __syncthreads();
        if (s + 2 < nStages) issueStage((s + 2) % 3, s + 2);

        const uint32_t* Sb = sm + st * STAGE;
        const uint32_t* Abase = Sb + t * 264;
        const uint32_t* Bbase = Sb + BOFF;
#pragma unroll
        for (int ks = 0; ks < 2; ks++) {
            uint4 afh[4];
            uint32_t bfh[4][2];
#pragma unroll
            for (int mti = 0; mti < 4; mti++)
                afh[mti] = *(const uint4*)(Abase + ks * 1056 + ((wrow * 4 + mti) * 8 + g) * 4);
#pragma unroll
            for (int nt = 0; nt < 4; nt++) {
                const int n0 = wcol * 32 + nt * 8 + g;
                bfh[nt][0] = Bbase[(ks * 8 + t) * 136 + n0];
                bfh[nt][1] = Bbase[(ks * 8 + t + 4) * 136 + n0];
            }
            if (!SPLIT) {
#pragma unroll
                for (int mti = 0; mti < 4; mti++)
#pragma unroll
                    for (int nt = 0; nt < 4; nt++)
                        mma16(acc[mti][nt], afh[mti].x, afh[mti].y, afh[mti].z, afh[mti].w,
                              bfh[nt][0], bfh[nt][1]);
            } else {
                uint4 afl[4];
                uint32_t bfl[4][2];
#pragma unroll
                for (int mti = 0; mti < 4; mti++)
                    afl[mti] = *(const uint4*)(Abase + AU + ks * 1056 +
                                               ((wrow * 4 + mti) * 8 + g) * 4);
#pragma unroll
                for (int nt = 0; nt < 4; nt++) {
                    const int n0 = wcol * 32 + nt * 8 + g;
                    bfl[nt][0] = Bbase[BU + (ks * 8 + t) * 136 + n0];
                    bfl[nt][1] = Bbase[BU + (ks * 8 + t + 4) * 136 + n0];
                }
#pragma unroll
                for (int mti = 0; mti < 4; mti++)
#pragma unroll
                    for (int nt = 0; nt < 4; nt++) {
                        mma16(acc[mti][nt], afh[mti].x, afh[mti].y, afh[mti].z, afh[mti].w,
                              bfl[nt][0], bfl[nt][1]);
                        mma16(acc[mti][nt], afl[mti].x, afl[mti].y, afl[mti].z, afl[mti].w,
                              bfh[nt][0], bfh[nt][1]);
                        mma16(acc[mti][nt], afh[mti].x, afh[mti].y, afh[mti].z, afh[mti].w,
                              bfh[nt][0], bfh[nt][1]);
                    }
            }
        }
        __syncthreads();
    }

    float* Ct = C + blockIdx.z * cPlane;
#pragma unroll
    for (int mti = 0; mti < 4; mti++) {
        const int row = bMt * 128 + wrow * 64 + mti * 16 + g;
#pragma unroll
        for (int nt = 0; nt < 4; nt++) {
            const int col = bN + wcol * 32 + nt * 8 + 2 * t;
            float* p = Ct + (size_t)row * ldc + col;
            p[0]                   = acc[mti][nt][0];
            p[1]                   = acc[mti][nt][1];
            p[(size_t)8 * ldc]     = acc[mti][nt][2];
            p[(size_t)8 * ldc + 1] = acc[mti][nt][3];
        }
    }
}

// ---------------- pack / elementwise kernels -------------------------------------

__device__ __forceinline__ void packFragRow(const float* __restrict__ src, int K,
                                            uint32_t* __restrict__ dsth,
                                            uint32_t* __restrict__ dstl,
                                            int ktiles, int kt, int mt, int tp) {
    const int mloc = tp >> 1, half = tp & 1;
    const float* s = src + (size_t)(mt * 128 + mloc) * K + kt * 16 + half * 8;
    const float4 v0 = *(const float4*)s;
    const float4 v1 = *(const float4*)(s + 4);
    const float v[8] = {v0.x, v0.y, v0.z, v0.w, v1.x, v1.y, v1.z, v1.w};
    const int mg   = (mloc & 7) | ((mloc >> 4) << 3);
    const int msel = (mloc >> 3) & 1;
    const int reg  = half * 2 + msel;
    const size_t base = ((size_t)mt * ktiles + kt) * 1024 + mg * 4 + reg;
#pragma unroll
    for (int tt = 0; tt < 4; tt++) {
        const uint32_t h = packbf(v[2 * tt], v[2 * tt + 1]);
        dsth[base + tt * 256] = h;
        if (dstl) dstl[base + tt * 256] = packres(v[2 * tt], v[2 * tt + 1], h);
    }
}

__global__ void packAdj_kernel(const float* __restrict__ adj) {
    packFragRow(adj, NN, g_adjp, nullptr, 192, blockIdx.x, blockIdx.y, threadIdx.x);
}
__global__ void packX_kernel(const float* __restrict__ x) {
    packFragRow(x, FIN, g_xh, g_xl, 32, blockIdx.x, blockIdx.y, threadIdx.x);
}

__global__ void packWpair_kernel() {
    const int i = blockIdx.x * 256 + threadIdx.x;   // over 256*1280
    const int r = i / NPACK;
    const int c = i % NPACK;
    const float v0 = g_WALL[(size_t)(2 * r) * NPACK + c];
    const float v1 = g_WALL[(size_t)(2 * r + 1) * NPACK + c];
    const uint32_t h = packbf(v0, v1);
    g_wh[i] = h;
    g_wl[i] = packres(v0, v1, h);
}

__global__ void rowsum_kernel(const float* __restrict__ adj, const float* __restrict__ hp,
                              float* __restrict__ dr, float* __restrict__ di) {
    __shared__ float sh[256];
    const int row = blockIdx.x;
    const float* a = adj + (size_t)row * NN;
    float s = 0.f;
    for (int c = threadIdx.x; c < NN; c += 256) s += a[c];
    sh[threadIdx.x] = s;
    __syncthreads();
    for (int o = 128; o > 0; o >>= 1) {
        if (threadIdx.x < o) sh[threadIdx.x] += sh[threadIdx.x + o];
        __syncthreads();
    }
    if (threadIdx.x == 0) {
        const float h = *hp;
        const float sv = h * (1.0f - sh[0]);
        const float inv = 1.0f / (sv * sv + 1.0f);
        dr[row] = sv * inv;
        di[row] = -inv;
    }
}

__global__ void packW_kernel(const float* __restrict__ w0,
                             const float* __restrict__ wr, const float* __restrict__ wi) {
    const int i = blockIdx.x * blockDim.x + threadIdx.x;
    const int r = i / NPACK;
    const int c = i % NPACK;
    float v;
    if (c < 256)        v = wr[(size_t)FIN * FOUT + r * FOUT + c];
    else if (c < 512)   v = wi[(size_t)FIN * FOUT + r * FOUT + (c - 256)];
    else if (c < 768)   v = wr[(size_t)r * FOUT + (c - 512)];
    else if (c < 1024)  v = wi[(size_t)r * FOUT + (c - 768)];
    else                v = w0[(size_t)r * FOUT + (c - 1024)];
    g_WALL[i] = v;
}

// Q = P2 (interleaved RIRI) ; Bbf0 = bf16 row-pairs of Q
__global__ void initQ_kernel() {
    const int i = blockIdx.x * 256 + threadIdx.x;   // over 1536*256
    const int r = i >> 8, j = i & 255;
    const int n0 = 2 * r, n1 = n0 + 1;
    const float q0r = g_P[(size_t)n0 * NPACK + j];
    const float q0i = g_P[(size_t)n0 * NPACK + 256 + j];
    const float q1r = g_P[(size_t)n1 * NPACK + j];
    const float q1i = g_P[(size_t)n1 * NPACK + 256 + j];
    *(float2*)&g_Q[(size_t)n0 * FB + 2 * j] = make_float2(q0r, q0i);
    *(float2*)&g_Q[(size_t)n1 * FB + 2 * j] = make_float2(q1r, q1i);
    *(uint2*)&g_Bbf0[(size_t)r * FB + 2 * j] =
        make_uint2(packbf(q0r, q1r), packbf(q0i, q1i));
}

// Q = P1 + Y (interleaved) ; Bbf1 = bf16 row-pairs of Q
__global__ void formQ_kernel() {
    const int i = blockIdx.x * 256 + threadIdx.x;   // over 1536*256
    const int r = i >> 8, j = i & 255;
    const int n0 = 2 * r, n1 = n0 + 1;
    const float2 y0 = *(const float2*)&g_Y[(size_t)n0 * FB + 2 * j];
    const float2 y1 = *(const float2*)&g_Y[(size_t)n1 * FB + 2 * j];
    const float q0r = g_P[(size_t)n0 * NPACK + 512 + j] + y0.x;
    const float q0i = g_P[(size_t)n0 * NPACK + 768 + j] + y0.y;
    const float q1r = g_P[(size_t)n1 * NPACK + 512 + j] + y1.x;
    const float q1i = g_P[(size_t)n1 * NPACK + 768 + j] + y1.y;
    *(float2*)&g_Q[(size_t)n0 * FB + 2 * j] = make_float2(q0r, q0i);
    *(float2*)&g_Q[(size_t)n1 * FB + 2 * j] = make_float2(q1r, q1i);
    *(uint2*)&g_Bbf1[(size_t)r * FB + 2 * j] =
        make_uint2(packbf(q0r, q1r), packbf(q0i, q1i));
}

// out = relu(out0 + 2*Re(Y)) ; out0 = g_P[:, 1024:1280], Y interleaved
__global__ void relu_kernel(float* __restrict__ out) {
    const int i = blockIdx.x * blockDim.x + threadIdx.x;
    const size_t r = i >> 8;
    const size_t c = i & 255;
    const float v = g_P[r * NPACK + 1024 + c] + 2.f * g_Y[r * FB + 2 * c];
    out[i] = v > 0.f ? v : 0.f;
}

// ---------------- orchestration --------------------------------------------------
#define SMEM_BIG   (3 * 4288 * 4)
#define SMEM_SPLIT (3 * 8576 * 4)

extern "C" void kernel_launch(void* const* d_in, const int* in_sizes, int n_in,
                              void* d_out, int out_size) {
    const float* x   = (const float*)d_in[0];
    const float* adj = (const float*)d_in[1];
    const float* hp  = (const float*)d_in[2];
    const float* w0  = (const float*)d_in[3];
    const float* wr  = (const float*)d_in[4];
    const float* wi  = (const float*)d_in[5];
    float* out = (float*)d_out;

    float *Pp, *Q, *Y, *XJ, *G, *dr, *di;
    uint32_t *adjp, *B0, *B1, *xh, *xl, *wh, *wl;
    int* cnt;
    cudaGetSymbolAddress((void**)&Pp, g_P);
    cudaGetSymbolAddress((void**)&Q, g_Q);
    cudaGetSymbolAddress((void**)&Y, g_Y);
    cudaGetSymbolAddress((void**)&XJ, g_XJ);
    cudaGetSymbolAddress((void**)&G, g_G);
    cudaGetSymbolAddress((void**)&dr, g_dr);
    cudaGetSymbolAddress((void**)&di, g_di);
    cudaGetSymbolAddress((void**)&adjp, g_adjp);
    cudaGetSymbolAddress((void**)&B0, g_Bbf0);
    cudaGetSymbolAddress((void**)&B1, g_Bbf1);
    cudaGetSymbolAddress((void**)&xh, g_xh);
    cudaGetSymbolAddress((void**)&xl, g_xl);
    cudaGetSymbolAddress((void**)&wh, g_wh);
    cudaGetSymbolAddress((void**)&wl, g_wl);
    cudaGetSymbolAddress((void**)&cnt, g_cnt);

    cudaFuncSetAttribute(gemm_fused<EPI_XJ>, cudaFuncAttributeMaxDynamicSharedMemorySize, SMEM_BIG);
    cudaFuncSetAttribute(gemm_fused<EPI_JAC>, cudaFuncAttributeMaxDynamicSharedMemorySize, SMEM_BIG);
    cudaFuncSetAttribute(gemm_pipe<true>, cudaFuncAttributeMaxDynamicSharedMemorySize, SMEM_SPLIT);

    rowsum_kernel<<<NN, 256>>>(adj, hp, dr, di);
    packW_kernel<<<(FIN * NPACK) / 256, 256>>>(w0, wr, wi);
    packWpair_kernel<<<(256 * NPACK) / 256, 256>>>();
    packX_kernel<<<dim3(32, 24), 256>>>(x);
    packAdj_kernel<<<dim3(192, 24), 256>>>(adj);

    // P = x @ WALL : [3072, 1280] = [P2 | P1 | out0] (split-bf16, fp32-grade)
    gemm_pipe<true><<<dim3(10, 24, 1), 256, SMEM_SPLIT>>>(xh, xl, wh, wl,
                                                          Pp, NPACK, NPACK, 32, 16, 0);
    initQ_kernel<<<1536, 256>>>();

    const dim3 gridBig(4, 24, 3);
    // applyK #1: Y = K @ P2
    gemm_fused<EPI_XJ><<<gridBig, 256, SMEM_BIG>>>(adjp, B0, G, cnt, hp, dr, di, B1, XJ, Y, Q);
    gemm_fused<EPI_JAC><<<gridBig, 256, SMEM_BIG>>>(adjp, B1, G, cnt, hp, dr, di, B0, XJ, Y, Q);
    gemm_fused<EPI_JAC><<<gridBig, 256, SMEM_BIG>>>(adjp, B0, G, cnt, hp, dr, di, B1, XJ, Y, Q);
    gemm_fused<EPI_JAC><<<gridBig, 256, SMEM_BIG>>>(adjp, B1, G, cnt, hp, dr, di, B0, XJ, Y, Q);

    // Q = P1 + Y ; B1 = bf16(Q)
    formQ_kernel<<<1536, 256>>>();

    // applyK #2: Y = K @ Q  (= csum)
    gemm_fused<EPI_XJ><<<gridBig, 256, SMEM_BIG>>>(adjp, B1, G, cnt, hp, dr, di, B0, XJ, Y, Q);
    gemm_fused<EPI_JAC><<<gridBig, 256, SMEM_BIG>>>(adjp, B0, G, cnt, hp, dr, di, B1, XJ, Y, Q);
    gemm_fused<EPI_JAC><<<gridBig, 256, SMEM_BIG>>>(adjp, B1, G, cnt, hp, dr, di, B0, XJ, Y, Q);
    gemm_fused<EPI_JAC><<<gridBig, 256, SMEM_BIG>>>(adjp, B0, G, cnt, hp, dr, di, B1, XJ, Y, Q);

    // out = relu(out0 + 2*Re(csum))
    relu_kernel<<<(NN * FOUT) / 256, 256>>>(out);
}

// round 10
// speedup vs baseline: 1.2440x; 1.2440x over previous
#include <cuda_runtime.h>
#include <cstdint>
#include <cstddef>

#define NN 3072
#define FB 512     // working block width (256 complex -> 512 real cols)
#define FOUT 256
#define FIN 512
#define NPACK 1280 // [wr1|wi1 | wr0|wi0 | w0]

// ---------------- scratch (device globals) -------------------------------------
__device__ __align__(1024) uint32_t g_adjp[(size_t)NN * NN / 2]; // bf16 fragment-tiled adj
__device__ __align__(1024) uint32_t g_Bbf[(NN / 2) * FB];        // bf16x2 interleaved B operand
__device__ __align__(1024) uint32_t g_xh[(size_t)NN * FIN / 2];  // x fragment-tiled bf16 hi
__device__ __align__(1024) uint32_t g_xl[(size_t)NN * FIN / 2];  // x fragment-tiled bf16 lo
__device__ __align__(1024) uint32_t g_wh[(FIN / 2) * NPACK];     // W pair-rows bf16 hi
__device__ __align__(1024) uint32_t g_wl[(FIN / 2) * NPACK];     // W pair-rows bf16 lo
__device__ __align__(128) float g_P[NN * NPACK];                 // packed projections
__device__ __align__(128) float g_Q[NN * FB];
__device__ __align__(128) float g_Y[NN * FB];
__device__ __align__(128) float g_XJ[NN * FB];
__device__ __align__(128) float g_G[3 * NN * FB];                // split-K partials
__device__ __align__(128) float g_dr[NN];
__device__ __align__(128) float g_di[NN];

// ---------------- helpers -------------------------------------------------------
__device__ __forceinline__ uint32_t packbf(float lo, float hi) {
    uint32_t d;
    asm("cvt.rn.bf16x2.f32 %0, %1, %2;" : "=r"(d) : "f"(hi), "f"(lo));
    return d;
}
__device__ __forceinline__ uint32_t packres(float lo, float hi, uint32_t h) {
    const float hl = __uint_as_float(h << 16);
    const float hh = __uint_as_float(h & 0xFFFF0000u);
    return packbf(lo - hl, hi - hh);
}
__device__ __forceinline__ uint32_t smem_u32(const void* p) {
    uint32_t a;
    asm("{ .reg .u64 t; cvta.to.shared.u64 t, %1; cvt.u32.u64 %0, t; }" : "=r"(a) : "l"(p));
    return a;
}
__device__ __forceinline__ void cpasync16(uint32_t dst, const void* src) {
    asm volatile("cp.async.cg.shared.global [%0], [%1], 16;" :: "r"(dst), "l"(src) : "memory");
}
__device__ __forceinline__ void mma16(float c[4],
                                      uint32_t a0, uint32_t a1, uint32_t a2, uint32_t a3,
                                      uint32_t b0, uint32_t b1) {
    asm volatile(
        "mma.sync.aligned.m16n8k16.row.col.f32.bf16.bf16.f32 "
        "{%0,%1,%2,%3}, {%4,%5,%6,%7}, {%8,%9}, {%0,%1,%2,%3};"
        : "+f"(c[0]), "+f"(c[1]), "+f"(c[2]), "+f"(c[3])
        : "r"(a0), "r"(a1), "r"(a2), "r"(a3), "r"(b0), "r"(b1));
}

// ================= BIG GEMM: bf16-resident, cp.async 4-stage, BK=32 =============
// G[z] = adj[:, zslice] @ Ybf[zslice, :]   (fp32 out, 128x128 CTA, 256 thr)
__global__ void __launch_bounds__(256, 2)
gemm_big(const uint32_t* __restrict__ Ap, const uint32_t* __restrict__ Bbf,
         float* __restrict__ C, size_t cPlane) {
    constexpr int STAGE = 4288;    // u32: A 2112 + B 16*136
    extern __shared__ __align__(16) uint32_t sm[];
    const uint32_t smb = smem_u32(sm);

    const int tid  = threadIdx.x;
    const int lane = tid & 31;
    const int warp = tid >> 5;
    const int wrow = warp >> 2;
    const int wcol = warp & 3;
    const int g    = lane >> 2;
    const int t    = lane & 3;
    const int bMt  = blockIdx.y;
    const int bN   = blockIdx.x * 128;
    const int kt0  = blockIdx.z * 64;

    float acc[4][4][4];
#pragma unroll
    for (int i = 0; i < 4; i++)
#pragma unroll
        for (int j = 0; j < 4; j++)
#pragma unroll
            for (int k = 0; k < 4; k++) acc[i][j][k] = 0.f;

    auto issueStage = [&](int st, int s) {
        const uint32_t stb = smb + st * (STAGE * 4);
        const int kt16 = kt0 + s * 2;
        const size_t atile = ((size_t)bMt * 192 + kt16) * 1024;
#pragma unroll
        for (int i = 0; i < 2; i++) {
            const int c = tid + i * 256;
            const int j = c >> 8, w = c & 255;
            cpasync16(stb + (uint32_t)(j * 1056 + (w >> 6) * 264 + (w & 63) * 4) * 4,
                      Ap + atile + c * 4);
        }
        const size_t brow = (size_t)kt16 * 8 * FB + bN;
#pragma unroll
        for (int i = 0; i < 2; i++) {
            const int c = tid + i * 256;
            const int row = c >> 5, c4 = (c & 31) * 4;
            cpasync16(stb + 8448 + (uint32_t)(row * 136 + c4) * 4,
                      Bbf + brow + (size_t)row * FB + c4);
        }
        asm volatile("cp.async.commit_group;" ::: "memory");
    };

    const int nT = 32;
    issueStage(0, 0);
    issueStage(1, 1);
    issueStage(2, 2);

    for (int s = 0; s < nT; s++) {
        const int st = s & 3;
        if (s <= nT - 3)      asm volatile("cp.async.wait_group 2;" ::: "memory");
        else if (s == nT - 2) asm volatile("cp.async.wait_group 1;" ::: "memory");
        else                  asm volatile("cp.async.wait_group 0;" ::: "memory");
        __syncthreads();
        if (s + 3 < nT) issueStage((s + 3) & 3, s + 3);

        const uint32_t* Abase = sm + st * STAGE + t * 264;
        const uint32_t* Bbase = sm + st * STAGE + 2112;
#pragma unroll
        for (int ks = 0; ks < 2; ks++) {
            uint4 afv[4];
            uint32_t bf[4][2];
#pragma unroll
            for (int mti = 0; mti < 4; mti++)
                afv[mti] = *(const uint4*)(Abase + ks * 1056 + ((wrow * 4 + mti) * 8 + g) * 4);
#pragma unroll
            for (int nt = 0; nt < 4; nt++) {
                const int n0 = wcol * 32 + nt * 8 + g;
                bf[nt][0] = Bbase[(ks * 8 + t) * 136 + n0];
                bf[nt][1] = Bbase[(ks * 8 + t + 4) * 136 + n0];
            }
#pragma unroll
            for (int mti = 0; mti < 4; mti++)
#pragma unroll
                for (int nt = 0; nt < 4; nt++)
                    mma16(acc[mti][nt], afv[mti].x, afv[mti].y, afv[mti].z, afv[mti].w,
                          bf[nt][0], bf[nt][1]);
        }
        __syncthreads();
    }

    float* Ct = C + blockIdx.z * cPlane;
#pragma unroll
    for (int mti = 0; mti < 4; mti++) {
        const int row = bMt * 128 + wrow * 64 + mti * 16 + g;
#pragma unroll
        for (int nt = 0; nt < 4; nt++) {
            const int col = bN + wcol * 32 + nt * 8 + 2 * t;
            float* p = Ct + (size_t)row * FB + col;
            p[0]                  = acc[mti][nt][0];
            p[1]                  = acc[mti][nt][1];
            p[(size_t)8 * FB]     = acc[mti][nt][2];
            p[(size_t)8 * FB + 1] = acc[mti][nt][3];
        }
    }
}

// ================= projection GEMM (split-bf16, 3-stage pipelined) ===============
__global__ void __launch_bounds__(256, 2)
gemm_proj(const uint32_t* __restrict__ Ah, const uint32_t* __restrict__ Al,
          const uint32_t* __restrict__ Bh, const uint32_t* __restrict__ Bl,
          float* __restrict__ C) {
    constexpr int AU = 2112;
    constexpr int BOFF = 4224;
    constexpr int BU = 16 * 136;
    constexpr int STAGE = BOFF + 2 * BU;   // 8576 u32

    extern __shared__ __align__(16) uint32_t sm[];
    const uint32_t smb = smem_u32(sm);

    const int tid  = threadIdx.x;
    const int lane = tid & 31;
    const int warp = tid >> 5;
    const int wrow = warp >> 2;
    const int wcol = warp & 3;
    const int g    = lane >> 2;
    const int t    = lane & 3;
    const int bMt  = blockIdx.y;
    const int bN   = blockIdx.x * 128;

    float acc[4][4][4];
#pragma unroll
    for (int i = 0; i < 4; i++)
#pragma unroll
        for (int j = 0; j < 4; j++)
#pragma unroll
            for (int k = 0; k < 4; k++) acc[i][j][k] = 0.f;

    auto issueStage = [&](int st, int s) {
        const uint32_t stb = smb + st * (STAGE * 4);
        const int kt16 = s * 2;
        const size_t atile = ((size_t)bMt * 32 + kt16) * 1024;
#pragma unroll
        for (int i = 0; i < 2; i++) {
            const int c = tid + i * 256;
            const int j = c >> 8, w = c & 255;
            const uint32_t off = (uint32_t)(j * 1056 + (w >> 6) * 264 + (w & 63) * 4) * 4;
            cpasync16(stb + off, Ah + atile + c * 4);
            cpasync16(stb + AU * 4 + off, Al + atile + c * 4);
        }
        const size_t brow = (size_t)kt16 * 8 * NPACK + bN;
#pragma unroll
        for (int i = 0; i < 2; i++) {
            const int c = tid + i * 256;
            const int row = c >> 5, c4 = (c & 31) * 4;
            const uint32_t off = (uint32_t)(row * 136 + c4) * 4;
            cpasync16(stb + BOFF * 4 + off, Bh + brow + (size_t)row * NPACK + c4);
            cpasync16(stb + (BOFF + BU) * 4 + off, Bl + brow + (size_t)row * NPACK + c4);
        }
        asm volatile("cp.async.commit_group;" ::: "memory");
    };

    const int nT = 16;
    issueStage(0, 0);
    issueStage(1, 1);

    for (int s = 0; s < nT; s++) {
        const int st = s % 3;
        if (s + 1 < nT) asm volatile("cp.async.wait_group 1;" ::: "memory");
        else            asm volatile("cp.async.wait_group 0;" ::: "memory");
        __syncthreads();
        if (s + 2 < nT) issueStage((s + 2) % 3, s + 2);

        const uint32_t* Sb = sm + st * STAGE;
        const uint32_t* Abase = Sb + t * 264;
        const uint32_t* Bbase = Sb + BOFF;
#pragma unroll
        for (int ks = 0; ks < 2; ks++) {
            uint4 afh[4], afl[4];
            uint32_t bfh[4][2], bfl[4][2];
#pragma unroll
            for (int mti = 0; mti < 4; mti++) {
                afh[mti] = *(const uint4*)(Abase + ks * 1056 + ((wrow * 4 + mti) * 8 + g) * 4);
                afl[mti] = *(const uint4*)(Abase + AU + ks * 1056 + ((wrow * 4 + mti) * 8 + g) * 4);
            }
#pragma unroll
            for (int nt = 0; nt < 4; nt++) {
                const int n0 = wcol * 32 + nt * 8 + g;
                bfh[nt][0] = Bbase[(ks * 8 + t) * 136 + n0];
                bfh[nt][1] = Bbase[(ks * 8 + t + 4) * 136 + n0];
                bfl[nt][0] = Bbase[BU + (ks * 8 + t) * 136 + n0];
                bfl[nt][1] = Bbase[BU + (ks * 8 + t + 4) * 136 + n0];
            }
#pragma unroll
            for (int mti = 0; mti < 4; mti++)
#pragma unroll
                for (int nt = 0; nt < 4; nt++) {
                    mma16(acc[mti][nt], afh[mti].x, afh[mti].y, afh[mti].z, afh[mti].w,
                          bfl[nt][0], bfl[nt][1]);
                    mma16(acc[mti][nt], afl[mti].x, afl[mti].y, afl[mti].z, afl[mti].w,
                          bfh[nt][0], bfh[nt][1]);
                    mma16(acc[mti][nt], afh[mti].x, afh[mti].y, afh[mti].z, afh[mti].w,
                          bfh[nt][0], bfh[nt][1]);
                }
        }
        __syncthreads();
    }

#pragma unroll
    for (int mti = 0; mti < 4; mti++) {
        const int row = bMt * 128 + wrow * 64 + mti * 16 + g;
#pragma unroll
        for (int nt = 0; nt < 4; nt++) {
            const int col = bN + wcol * 32 + nt * 8 + 2 * t;
            float* p = C + (size_t)row * NPACK + col;
            p[0]                     = acc[mti][nt][0];
            p[1]                     = acc[mti][nt][1];
            p[(size_t)8 * NPACK]     = acc[mti][nt][2];
            p[(size_t)8 * NPACK + 1] = acc[mti][nt][3];
        }
    }
}

// ---------------- merged prep kernel ----------------------------------------------
// blocks [0,3072): rowsum | [3072,4352): packW hi/lo | [4352,5120): packX | [5120,9728): packAdj
__device__ __forceinline__ float wallVal(const float* __restrict__ w0,
                                         const float* __restrict__ wr,
                                         const float* __restrict__ wi, int r, int c) {
    if (c < 256)       return wr[(size_t)FIN * FOUT + (size_t)r * FOUT + c];
    if (c < 512)       return wi[(size_t)FIN * FOUT + (size_t)r * FOUT + (c - 256)];
    if (c < 768)       return wr[(size_t)r * FOUT + (c - 512)];
    if (c < 1024)      return wi[(size_t)r * FOUT + (c - 768)];
    return w0[(size_t)r * FOUT + (c - 1024)];
}

__device__ __forceinline__ void packFragRow(const float* __restrict__ src, int K,
                                            uint32_t* __restrict__ dsth,
                                            uint32_t* __restrict__ dstl,
                                            int ktiles, int kt, int mt, int tp) {
    const int mloc = tp >> 1, half = tp & 1;
    const float* s = src + (size_t)(mt * 128 + mloc) * K + kt * 16 + half * 8;
    const float4 v0 = *(const float4*)s;
    const float4 v1 = *(const float4*)(s + 4);
    const float v[8] = {v0.x, v0.y, v0.z, v0.w, v1.x, v1.y, v1.z, v1.w};
    const int mg   = (mloc & 7) | ((mloc >> 4) << 3);
    const int msel = (mloc >> 3) & 1;
    const int reg  = half * 2 + msel;
    const size_t base = ((size_t)mt * ktiles + kt) * 1024 + mg * 4 + reg;
#pragma unroll
    for (int tt = 0; tt < 4; tt++) {
        const uint32_t h = packbf(v[2 * tt], v[2 * tt + 1]);
        dsth[base + tt * 256] = h;
        if (dstl) dstl[base + tt * 256] = packres(v[2 * tt], v[2 * tt + 1], h);
    }
}

__global__ void prep_kernel(const float* __restrict__ adj, const float* __restrict__ hp,
                            const float* __restrict__ x,
                            const float* __restrict__ w0, const float* __restrict__ wr,
                            const float* __restrict__ wi) {
    const int b = blockIdx.x;
    if (b < 3072) {
        // rowsum -> diag preconditioner
        __shared__ float sh[256];
        const float* a = adj + (size_t)b * NN;
        float s = 0.f;
        for (int c = threadIdx.x; c < NN; c += 256) s += a[c];
        sh[threadIdx.x] = s;
        __syncthreads();
        for (int o = 128; o > 0; o >>= 1) {
            if (threadIdx.x < o) sh[threadIdx.x] += sh[threadIdx.x + o];
            __syncthreads();
        }
        if (threadIdx.x == 0) {
            const float h = *hp;
            const float sv = h * (1.0f - sh[0]);
            const float inv = 1.0f / (sv * sv + 1.0f);
            g_dr[b] = sv * inv;
            g_di[b] = -inv;
        }
    } else if (b < 4352) {
        // W pair-rows hi/lo direct
        const int i = (b - 3072) * 256 + threadIdx.x;   // over 256*NPACK
        const int r = i / NPACK;
        const int c = i % NPACK;
        const float v0 = wallVal(w0, wr, wi, 2 * r, c);
        const float v1 = wallVal(w0, wr, wi, 2 * r + 1, c);
        const uint32_t h = packbf(v0, v1);
        g_wh[i] = h;
        g_wl[i] = packres(v0, v1, h);
    } else if (b < 5120) {
        const int p = b - 4352;                         // 32 x 24
        packFragRow(x, FIN, g_xh, g_xl, 32, p & 31, p >> 5, threadIdx.x);
    } else {
        const int p = b - 5120;                         // 192 x 24
        packFragRow(adj, NN, g_adjp, nullptr, 192, p % 192, p / 192, threadIdx.x);
    }
}

// ---------------- elementwise kernels --------------------------------------------

// Bbf[r][c] = bf16x2(P2[2r][c], P2[2r+1][c])
__global__ void packP2_kernel() {
    const int i = blockIdx.x * 256 + threadIdx.x;   // over 1536*512
    const int r = i >> 9;
    const int c = i & 511;
    g_Bbf[(size_t)r * FB + c] = packbf(g_P[(size_t)(2 * r) * NPACK + c],
                                       g_P[(size_t)(2 * r + 1) * NPACK + c]);
}

__global__ void xj_kernel(const float* __restrict__ hp,
                          const float* __restrict__ Qsrc, int ldq) {
    const int i = blockIdx.x * 256 + threadIdx.x;   // over 1536*256
    const int r = i >> 8;
    const int c = i & 255;
    const int n0 = 2 * r, n1 = 2 * r + 1;
    const float h = *hp;
    const size_t P = (size_t)NN * FB;
    const size_t i0r = (size_t)n0 * FB + c, i0i = i0r + 256;
    const size_t i1r = (size_t)n1 * FB + c, i1i = i1r + 256;
    const float GR0 = g_G[i0r] + g_G[i0r + P] + g_G[i0r + 2 * P];
    const float GI0 = g_G[i0i] + g_G[i0i + P] + g_G[i0i + 2 * P];
    const float GR1 = g_G[i1r] + g_G[i1r + P] + g_G[i1r + 2 * P];
    const float GI1 = g_G[i1i] + g_G[i1i + P] + g_G[i1i + 2 * P];
    const float q0r = Qsrc[(size_t)n0 * ldq + c], q0i = Qsrc[(size_t)n0 * ldq + c + 256];
    const float q1r = Qsrc[(size_t)n1 * ldq + c], q1i = Qsrc[(size_t)n1 * ldq + c + 256];
    const float x0r = h * q0r - h * GR0 + q0i;
    const float x0i = h * q0i - h * GI0 - q0r;
    const float x1r = h * q1r - h * GR1 + q1i;
    const float x1i = h * q1i - h * GI1 - q1r;
    g_XJ[i0r] = x0r; g_XJ[i0i] = x0i; g_XJ[i1r] = x1r; g_XJ[i1i] = x1i;
    g_Y[i0r] = x0r;  g_Y[i0i] = x0i;  g_Y[i1r] = x1r;  g_Y[i1i] = x1i;
    g_Bbf[(size_t)r * FB + c]       = packbf(x0r, x1r);
    g_Bbf[(size_t)r * FB + c + 256] = packbf(x0i, x1i);
}

// LAST=1: final Jacobi iteration — skip Bbf/Y writes, emit relu output directly.
template <int LAST>
__global__ void jacobi_kernel(const float* __restrict__ hp,
                              const float* __restrict__ dr, const float* __restrict__ di,
                              float* __restrict__ out) {
    const int i = blockIdx.x * 256 + threadIdx.x;
    const int r = i >> 8;
    const int c = i & 255;
    const int n0 = 2 * r, n1 = 2 * r + 1;
    const float h = *hp;
    const size_t P = (size_t)NN * FB;
    const size_t i0r = (size_t)n0 * FB + c, i0i = i0r + 256;
    const size_t i1r = (size_t)n1 * FB + c, i1i = i1r + 256;
    const float GR0 = g_G[i0r] + g_G[i0r + P] + g_G[i0r + 2 * P];
    const float GI0 = g_G[i0i] + g_G[i0i + P] + g_G[i0i + 2 * P];
    const float GR1 = g_G[i1r] + g_G[i1r + P] + g_G[i1r + 2 * P];
    const float GI1 = g_G[i1i] + g_G[i1i + P] + g_G[i1i + 2 * P];
    const float y0r = g_Y[i0r], y0i = g_Y[i0i];
    const float y1r = g_Y[i1r], y1i = g_Y[i1i];
    const float r0r = g_XJ[i0r] - (h * y0r - h * GR0 - y0i);
    const float r0i = g_XJ[i0i] - (h * y0i - h * GI0 + y0r);
    const float r1r = g_XJ[i1r] - (h * y1r - h * GR1 - y1i);
    const float r1i = g_XJ[i1i] - (h * y1i - h * GI1 + y1r);
    const float d0r = dr[n0], d0i = di[n0];
    const float d1r = dr[n1], d1i = di[n1];
    const float ny0r = y0r + d0r * r0r - d0i * r0i;
    const float ny0i = y0i + d0r * r0i + d0i * r0r;
    const float ny1r = y1r + d1r * r1r - d1i * r1i;
    const float ny1i = y1i + d1r * r1i + d1i * r1r;
    if (LAST) {
        const float v0 = g_P[(size_t)n0 * NPACK + 1024 + c] + 2.f * ny0r;
        const float v1 = g_P[(size_t)n1 * NPACK + 1024 + c] + 2.f * ny1r;
        out[(size_t)n0 * FOUT + c] = v0 > 0.f ? v0 : 0.f;
        out[(size_t)n1 * FOUT + c] = v1 > 0.f ? v1 : 0.f;
    } else {
        g_Y[i0r] = ny0r; g_Y[i0i] = ny0i; g_Y[i1r] = ny1r; g_Y[i1i] = ny1i;
        g_Bbf[(size_t)r * FB + c]       = packbf(ny0r, ny1r);
        g_Bbf[(size_t)r * FB + c + 256] = packbf(ny0i, ny1i);
    }
}

// Q = P1 + Y ; Bbf = bf16 pairs of Q
__global__ void formQ_kernel() {
    const int i = blockIdx.x * 256 + threadIdx.x;   // over 1536*512
    const int r = i >> 9;
    const int c = i & 511;
    const int n0 = 2 * r, n1 = 2 * r + 1;
    const float q0 = g_P[(size_t)n0 * NPACK + 512 + c] + g_Y[(size_t)n0 * FB + c];
    const float q1 = g_P[(size_t)n1 * NPACK + 512 + c] + g_Y[(size_t)n1 * FB + c];
    g_Q[(size_t)n0 * FB + c] = q0;
    g_Q[(size_t)n1 * FB + c] = q1;
    g_Bbf[(size_t)r * FB + c] = packbf(q0, q1);
}

// ---------------- orchestration --------------------------------------------------
#define SMEM_BIG   (4 * 4288 * 4)
#define SMEM_PROJ  (3 * 8576 * 4)

extern "C" void kernel_launch(void* const* d_in, const int* in_sizes, int n_in,
                              void* d_out, int out_size) {
    const float* x   = (const float*)d_in[0];
    const float* adj = (const float*)d_in[1];
    const float* hp  = (const float*)d_in[2];
    const float* w0  = (const float*)d_in[3];
    const float* wr  = (const float*)d_in[4];
    const float* wi  = (const float*)d_in[5];
    float* out = (float*)d_out;

    float *Pp, *Q, *Y, *G, *dr, *di;
    uint32_t *adjp, *Bbf, *xh, *xl, *wh, *wl;
    cudaGetSymbolAddress((void**)&Pp, g_P);
    cudaGetSymbolAddress((void**)&Q, g_Q);
    cudaGetSymbolAddress((void**)&Y, g_Y);
    cudaGetSymbolAddress((void**)&G, g_G);
    cudaGetSymbolAddress((void**)&dr, g_dr);
    cudaGetSymbolAddress((void**)&di, g_di);
    cudaGetSymbolAddress((void**)&adjp, g_adjp);
    cudaGetSymbolAddress((void**)&Bbf, g_Bbf);
    cudaGetSymbolAddress((void**)&xh, g_xh);
    cudaGetSymbolAddress((void**)&xl, g_xl);
    cudaGetSymbolAddress((void**)&wh, g_wh);
    cudaGetSymbolAddress((void**)&wl, g_wl);

    cudaFuncSetAttribute(gemm_big,  cudaFuncAttributeMaxDynamicSharedMemorySize, SMEM_BIG);
    cudaFuncSetAttribute(gemm_proj, cudaFuncAttributeMaxDynamicSharedMemorySize, SMEM_PROJ);

    // merged prep: rowsum + packW(hi/lo) + packX + packAdj
    prep_kernel<<<9728, 256>>>(adj, hp, x, w0, wr, wi);

    // P = x @ WALL : [3072, 1280] = [P2 | P1 | out0] (split-bf16, fp32-grade)
    gemm_proj<<<dim3(10, 24, 1), 256, SMEM_PROJ>>>(xh, xl, wh, wl, Pp);

    // Bbf = bf16(P2)
    packP2_kernel<<<(1536 * 512) / 256, 256>>>();

    const dim3 gridBig(4, 24, 3);
    const size_t PL = (size_t)NN * FB;

    // applyK #1: Y = K @ P2
    gemm_big<<<gridBig, 256, SMEM_BIG>>>(adjp, Bbf, G, PL);
    xj_kernel<<<1536, 256>>>(hp, Pp, NPACK);
    for (int it = 0; it < 3; it++) {
        gemm_big<<<gridBig, 256, SMEM_BIG>>>(adjp, Bbf, G, PL);
        jacobi_kernel<0><<<1536, 256>>>(hp, dr, di, out);
    }

    // Q = P1 + Y ; Bbf = bf16(Q)
    formQ_kernel<<<(1536 * 512) / 256, 256>>>();

    // applyK #2: Y = K @ Q  (= csum)
    gemm_big<<<gridBig, 256, SMEM_BIG>>>(adjp, Bbf, G, PL);
    xj_kernel<<<1536, 256>>>(hp, Q, FB);
    for (int it = 0; it < 2; it++) {
        gemm_big<<<gridBig, 256, SMEM_BIG>>>(adjp, Bbf, G, PL);
        jacobi_kernel<0><<<1536, 256>>>(hp, dr, di, out);
    }
    gemm_big<<<gridBig, 256, SMEM_BIG>>>(adjp, Bbf, G, PL);
    jacobi_kernel<1><<<1536, 256>>>(hp, dr, di, out);   // fused relu epilogue
}

// round 11
// speedup vs baseline: 1.2692x; 1.0203x over previous
#include <cuda_runtime.h>
#include <cstdint>
#include <cstddef>

#define NN 3072
#define FB 512     // working block width (256 complex -> 512 real cols)
#define FOUT 256
#define FIN 512
#define NPACK 1280 // [wr1|wi1 | wr0|wi0 | w0]

// ---------------- scratch (device globals) -------------------------------------
__device__ __align__(1024) uint32_t g_adjp[(size_t)NN * NN / 2]; // bf16 fragment-tiled adj
__device__ __align__(1024) uint32_t g_Bbf[(NN / 2) * FB];        // bf16x2 interleaved B operand
__device__ __align__(1024) uint32_t g_xh[(size_t)NN * FIN / 2];  // x fragment-tiled bf16 hi
__device__ __align__(1024) uint32_t g_xl[(size_t)NN * FIN / 2];  // x fragment-tiled bf16 lo
__device__ __align__(1024) uint32_t g_wh[(FIN / 2) * NPACK];     // W pair-rows bf16 hi
__device__ __align__(1024) uint32_t g_wl[(FIN / 2) * NPACK];     // W pair-rows bf16 lo
__device__ __align__(128) float g_P[NN * NPACK];                 // packed projections
__device__ __align__(128) float g_Q[NN * FB];
__device__ __align__(128) float g_Y[NN * FB];
__device__ __align__(128) float g_XJ[NN * FB];
__device__ __align__(128) float g_G[3 * NN * FB];                // split-K partials
__device__ __align__(128) float g_dr[NN];
__device__ __align__(128) float g_di[NN];

// ---------------- helpers -------------------------------------------------------
__device__ __forceinline__ uint32_t packbf(float lo, float hi) {
    uint32_t d;
    asm("cvt.rn.bf16x2.f32 %0, %1, %2;" : "=r"(d) : "f"(hi), "f"(lo));
    return d;
}
__device__ __forceinline__ uint32_t packres(float lo, float hi, uint32_t h) {
    const float hl = __uint_as_float(h << 16);
    const float hh = __uint_as_float(h & 0xFFFF0000u);
    return packbf(lo - hl, hi - hh);
}
__device__ __forceinline__ uint32_t smem_u32(const void* p) {
    uint32_t a;
    asm("{ .reg .u64 t; cvta.to.shared.u64 t, %1; cvt.u32.u64 %0, t; }" : "=r"(a) : "l"(p));
    return a;
}
__device__ __forceinline__ void cpasync16(uint32_t dst, const void* src) {
    asm volatile("cp.async.cg.shared.global [%0], [%1], 16;" :: "r"(dst), "l"(src) : "memory");
}
__device__ __forceinline__ void mma16(float c[4],
                                      uint32_t a0, uint32_t a1, uint32_t a2, uint32_t a3,
                                      uint32_t b0, uint32_t b1) {
    asm volatile(
        "mma.sync.aligned.m16n8k16.row.col.f32.bf16.bf16.f32 "
        "{%0,%1,%2,%3}, {%4,%5,%6,%7}, {%8,%9}, {%0,%1,%2,%3};"
        : "+f"(c[0]), "+f"(c[1]), "+f"(c[2]), "+f"(c[3])
        : "r"(a0), "r"(a1), "r"(a2), "r"(a3), "r"(b0), "r"(b1));
}

// ================= BIG GEMM: bf16-resident, cp.async 4-stage, BK=32 =============
// G[z] = adj[:, zslice] @ Ybf[zslice, :]   (fp32 out, 128x128 CTA, 256 thr)
__global__ void __launch_bounds__(256, 2)
gemm_big(const uint32_t* __restrict__ Ap, const uint32_t* __restrict__ Bbf,
         float* __restrict__ C, size_t cPlane) {
    constexpr int STAGE = 4288;    // u32: A 2112 + B 16*136
    extern __shared__ __align__(16) uint32_t sm[];
    const uint32_t smb = smem_u32(sm);

    const int tid  = threadIdx.x;
    const int lane = tid & 31;
    const int warp = tid >> 5;
    const int wrow = warp >> 2;
    const int wcol = warp & 3;
    const int g    = lane >> 2;
    const int t    = lane & 3;
    const int bMt  = blockIdx.y;
    const int bN   = blockIdx.x * 128;
    const int kt0  = blockIdx.z * 64;

    float acc[4][4][4];
#pragma unroll
    for (int i = 0; i < 4; i++)
#pragma unroll
        for (int j = 0; j < 4; j++)
#pragma unroll
            for (int k = 0; k < 4; k++) acc[i][j][k] = 0.f;

    auto issueStage = [&](int st, int s) {
        const uint32_t stb = smb + st * (STAGE * 4);
        const int kt16 = kt0 + s * 2;
        const size_t atile = ((size_t)bMt * 192 + kt16) * 1024;
#pragma unroll
        for (int i = 0; i < 2; i++) {
            const int c = tid + i * 256;
            const int j = c >> 8, w = c & 255;
            cpasync16(stb + (uint32_t)(j * 1056 + (w >> 6) * 264 + (w & 63) * 4) * 4,
                      Ap + atile + c * 4);
        }
        const size_t brow = (size_t)kt16 * 8 * FB + bN;
#pragma unroll
        for (int i = 0; i < 2; i++) {
            const int c = tid + i * 256;
            const int row = c >> 5, c4 = (c & 31) * 4;
            cpasync16(stb + 8448 + (uint32_t)(row * 136 + c4) * 4,
                      Bbf + brow + (size_t)row * FB + c4);
        }
        asm volatile("cp.async.commit_group;" ::: "memory");
    };

    const int nT = 32;
    issueStage(0, 0);
    issueStage(1, 1);
    issueStage(2, 2);

    for (int s = 0; s < nT; s++) {
        const int st = s & 3;
        if (s <= nT - 3)      asm volatile("cp.async.wait_group 2;" ::: "memory");
        else if (s == nT - 2) asm volatile("cp.async.wait_group 1;" ::: "memory");
        else                  asm volatile("cp.async.wait_group 0;" ::: "memory");
        __syncthreads();
        // safe: buffer (s+3)&3 was last read at iter s-1, completed by all
        // warps before the barrier above. Single barrier per stage.
        if (s + 3 < nT) issueStage((s + 3) & 3, s + 3);

        const uint32_t* Abase = sm + st * STAGE + t * 264;
        const uint32_t* Bbase = sm + st * STAGE + 2112;
#pragma unroll
        for (int ks = 0; ks < 2; ks++) {
            uint4 afv[4];
            uint32_t bf[4][2];
#pragma unroll
            for (int mti = 0; mti < 4; mti++)
                afv[mti] = *(const uint4*)(Abase + ks * 1056 + ((wrow * 4 + mti) * 8 + g) * 4);
#pragma unroll
            for (int nt = 0; nt < 4; nt++) {
                const int n0 = wcol * 32 + nt * 8 + g;
                bf[nt][0] = Bbase[(ks * 8 + t) * 136 + n0];
                bf[nt][1] = Bbase[(ks * 8 + t + 4) * 136 + n0];
            }
#pragma unroll
            for (int mti = 0; mti < 4; mti++)
#pragma unroll
                for (int nt = 0; nt < 4; nt++)
                    mma16(acc[mti][nt], afv[mti].x, afv[mti].y, afv[mti].z, afv[mti].w,
                          bf[nt][0], bf[nt][1]);
        }
    }

    float* Ct = C + blockIdx.z * cPlane;
#pragma unroll
    for (int mti = 0; mti < 4; mti++) {
        const int row = bMt * 128 + wrow * 64 + mti * 16 + g;
#pragma unroll
        for (int nt = 0; nt < 4; nt++) {
            const int col = bN + wcol * 32 + nt * 8 + 2 * t;
            float* p = Ct + (size_t)row * FB + col;
            p[0]                  = acc[mti][nt][0];
            p[1]                  = acc[mti][nt][1];
            p[(size_t)8 * FB]     = acc[mti][nt][2];
            p[(size_t)8 * FB + 1] = acc[mti][nt][3];
        }
    }
}

// ================= projection GEMM (split-bf16, 3-stage) + fused packP2 ==========
__global__ void __launch_bounds__(256, 2)
gemm_proj(const uint32_t* __restrict__ Ah, const uint32_t* __restrict__ Al,
          const uint32_t* __restrict__ Bh, const uint32_t* __restrict__ Bl,
          float* __restrict__ C, uint32_t* __restrict__ Bout) {
    constexpr int AU = 2112;
    constexpr int BOFF = 4224;
    constexpr int BU = 16 * 136;
    constexpr int STAGE = BOFF + 2 * BU;   // 8576 u32

    extern __shared__ __align__(16) uint32_t sm[];
    const uint32_t smb = smem_u32(sm);

    const int tid  = threadIdx.x;
    const int lane = tid & 31;
    const int warp = tid >> 5;
    const int wrow = warp >> 2;
    const int wcol = warp & 3;
    const int g    = lane >> 2;
    const int t    = lane & 3;
    const int bMt  = blockIdx.y;
    const int bN   = blockIdx.x * 128;

    float acc[4][4][4];
#pragma unroll
    for (int i = 0; i < 4; i++)
#pragma unroll
        for (int j = 0; j < 4; j++)
#pragma unroll
            for (int k = 0; k < 4; k++) acc[i][j][k] = 0.f;

    auto issueStage = [&](int st, int s) {
        const uint32_t stb = smb + st * (STAGE * 4);
        const int kt16 = s * 2;
        const size_t atile = ((size_t)bMt * 32 + kt16) * 1024;
#pragma unroll
        for (int i = 0; i < 2; i++) {
            const int c = tid + i * 256;
            const int j = c >> 8, w = c & 255;
            const uint32_t off = (uint32_t)(j * 1056 + (w >> 6) * 264 + (w & 63) * 4) * 4;
            cpasync16(stb + off, Ah + atile + c * 4);
            cpasync16(stb + AU * 4 + off, Al + atile + c * 4);
        }
        const size_t brow = (size_t)kt16 * 8 * NPACK + bN;
#pragma unroll
        for (int i = 0; i < 2; i++) {
            const int c = tid + i * 256;
            const int row = c >> 5, c4 = (c & 31) * 4;
            const uint32_t off = (uint32_t)(row * 136 + c4) * 4;
            cpasync16(stb + BOFF * 4 + off, Bh + brow + (size_t)row * NPACK + c4);
            cpasync16(stb + (BOFF + BU) * 4 + off, Bl + brow + (size_t)row * NPACK + c4);
        }
        asm volatile("cp.async.commit_group;" ::: "memory");
    };

    const int nT = 16;
    issueStage(0, 0);
    issueStage(1, 1);

    for (int s = 0; s < nT; s++) {
        const int st = s % 3;
        if (s + 1 < nT) asm volatile("cp.async.wait_group 1;" ::: "memory");
        else            asm volatile("cp.async.wait_group 0;" ::: "memory");
        __syncthreads();
        if (s + 2 < nT) issueStage((s + 2) % 3, s + 2);

        const uint32_t* Sb = sm + st * STAGE;
        const uint32_t* Abase = Sb + t * 264;
        const uint32_t* Bbase = Sb + BOFF;
#pragma unroll
        for (int ks = 0; ks < 2; ks++) {
            uint4 afh[4], afl[4];
            uint32_t bfh[4][2], bfl[4][2];
#pragma unroll
            for (int mti = 0; mti < 4; mti++) {
                afh[mti] = *(const uint4*)(Abase + ks * 1056 + ((wrow * 4 + mti) * 8 + g) * 4);
                afl[mti] = *(const uint4*)(Abase + AU + ks * 1056 + ((wrow * 4 + mti) * 8 + g) * 4);
            }
#pragma unroll
            for (int nt = 0; nt < 4; nt++) {
                const int n0 = wcol * 32 + nt * 8 + g;
                bfh[nt][0] = Bbase[(ks * 8 + t) * 136 + n0];
                bfh[nt][1] = Bbase[(ks * 8 + t + 4) * 136 + n0];
                bfl[nt][0] = Bbase[BU + (ks * 8 + t) * 136 + n0];
                bfl[nt][1] = Bbase[BU + (ks * 8 + t + 4) * 136 + n0];
            }
#pragma unroll
            for (int mti = 0; mti < 4; mti++)
#pragma unroll
                for (int nt = 0; nt < 4; nt++) {
                    mma16(acc[mti][nt], afh[mti].x, afh[mti].y, afh[mti].z, afh[mti].w,
                          bfl[nt][0], bfl[nt][1]);
                    mma16(acc[mti][nt], afl[mti].x, afl[mti].y, afl[mti].z, afl[mti].w,
                          bfh[nt][0], bfh[nt][1]);
                    mma16(acc[mti][nt], afh[mti].x, afh[mti].y, afh[mti].z, afh[mti].w,
                          bfh[nt][0], bfh[nt][1]);
                }
        }
    }

#pragma unroll
    for (int mti = 0; mti < 4; mti++) {
        const int row = bMt * 128 + wrow * 64 + mti * 16 + g;
#pragma unroll
        for (int nt = 0; nt < 4; nt++) {
            const int col = bN + wcol * 32 + nt * 8 + 2 * t;
            float* p = C + (size_t)row * NPACK + col;
            p[0]                     = acc[mti][nt][0];
            p[1]                     = acc[mti][nt][1];
            p[(size_t)8 * NPACK]     = acc[mti][nt][2];
            p[(size_t)8 * NPACK + 1] = acc[mti][nt][3];
        }
    }

    // fused packP2: P2 block (cols 0..511) also emits the bf16 B operand
    if (blockIdx.x < 4) {
#pragma unroll
        for (int mti = 0; mti < 4; mti++) {
            const int row = bMt * 128 + wrow * 64 + mti * 16 + g;
#pragma unroll
            for (int nt = 0; nt < 4; nt++) {
                const int col = bN + wcol * 32 + nt * 8 + 2 * t;
                const float v00 = acc[mti][nt][0], v01 = acc[mti][nt][1];
                const float v10 = acc[mti][nt][2], v11 = acc[mti][nt][3];
                const float o00 = __shfl_xor_sync(0xffffffffu, v00, 4);
                const float o01 = __shfl_xor_sync(0xffffffffu, v01, 4);
                const float o10 = __shfl_xor_sync(0xffffffffu, v10, 4);
                const float o11 = __shfl_xor_sync(0xffffffffu, v11, 4);
                if (!(g & 1)) {
                    *(uint2*)&Bout[(size_t)(row >> 1) * FB + col] =
                        make_uint2(packbf(v00, o00), packbf(v01, o01));
                    *(uint2*)&Bout[(size_t)((row + 8) >> 1) * FB + col] =
                        make_uint2(packbf(v10, o10), packbf(v11, o11));
                }
            }
        }
    }
}

// ---------------- merged prep kernel ----------------------------------------------
__device__ __forceinline__ float wallVal(const float* __restrict__ w0,
                                         const float* __restrict__ wr,
                                         const float* __restrict__ wi, int r, int c) {
    if (c < 256)       return wr[(size_t)FIN * FOUT + (size_t)r * FOUT + c];
    if (c < 512)       return wi[(size_t)FIN * FOUT + (size_t)r * FOUT + (c - 256)];
    if (c < 768)       return wr[(size_t)r * FOUT + (c - 512)];
    if (c < 1024)      return wi[(size_t)r * FOUT + (c - 768)];
    return w0[(size_t)r * FOUT + (c - 1024)];
}

__device__ __forceinline__ void packFragRow(const float* __restrict__ src, int K,
                                            uint32_t* __restrict__ dsth,
                                            uint32_t* __restrict__ dstl,
                                            int ktiles, int kt, int mt, int tp) {
    const int mloc = tp >> 1, half = tp & 1;
    const float* s = src + (size_t)(mt * 128 + mloc) * K + kt * 16 + half * 8;
    const float4 v0 = *(const float4*)s;
    const float4 v1 = *(const float4*)(s + 4);
    const float v[8] = {v0.x, v0.y, v0.z, v0.w, v1.x, v1.y, v1.z, v1.w};
    const int mg   = (mloc & 7) | ((mloc >> 4) << 3);
    const int msel = (mloc >> 3) & 1;
    const int reg  = half * 2 + msel;
    const size_t base = ((size_t)mt * ktiles + kt) * 1024 + mg * 4 + reg;
#pragma unroll
    for (int tt = 0; tt < 4; tt++) {
        const uint32_t h = packbf(v[2 * tt], v[2 * tt + 1]);
        dsth[base + tt * 256] = h;
        if (dstl) dstl[base + tt * 256] = packres(v[2 * tt], v[2 * tt + 1], h);
    }
}

__global__ void prep_kernel(const float* __restrict__ adj, const float* __restrict__ hp,
                            const float* __restrict__ x,
                            const float* __restrict__ w0, const float* __restrict__ wr,
                            const float* __restrict__ wi) {
    const int b = blockIdx.x;
    if (b < 3072) {
        __shared__ float sh[256];
        const float* a = adj + (size_t)b * NN;
        float s = 0.f;
        for (int c = threadIdx.x; c < NN; c += 256) s += a[c];
        sh[threadIdx.x] = s;
        __syncthreads();
        for (int o = 128; o > 0; o >>= 1) {
            if (threadIdx.x < o) sh[threadIdx.x] += sh[threadIdx.x + o];
            __syncthreads();
        }
        if (threadIdx.x == 0) {
            const float h = *hp;
            const float sv = h * (1.0f - sh[0]);
            const float inv = 1.0f / (sv * sv + 1.0f);
            g_dr[b] = sv * inv;
            g_di[b] = -inv;
        }
    } else if (b < 4352) {
        const int i = (b - 3072) * 256 + threadIdx.x;
        const int r = i / NPACK;
        const int c = i % NPACK;
        const float v0 = wallVal(w0, wr, wi, 2 * r, c);
        const float v1 = wallVal(w0, wr, wi, 2 * r + 1, c);
        const uint32_t h = packbf(v0, v1);
        g_wh[i] = h;
        g_wl[i] = packres(v0, v1, h);
    } else if (b < 5120) {
        const int p = b - 4352;
        packFragRow(x, FIN, g_xh, g_xl, 32, p & 31, p >> 5, threadIdx.x);
    } else {
        const int p = b - 5120;
        packFragRow(adj, NN, g_adjp, nullptr, 192, p % 192, p / 192, threadIdx.x);
    }
}

// ---------------- elementwise kernels --------------------------------------------

__global__ void xj_kernel(const float* __restrict__ hp,
                          const float* __restrict__ Qsrc, int ldq) {
    const int i = blockIdx.x * 256 + threadIdx.x;   // over 1536*256
    const int r = i >> 8;
    const int c = i & 255;
    const int n0 = 2 * r, n1 = 2 * r + 1;
    const float h = *hp;
    const size_t P = (size_t)NN * FB;
    const size_t i0r = (size_t)n0 * FB + c, i0i = i0r + 256;
    const size_t i1r = (size_t)n1 * FB + c, i1i = i1r + 256;
    const float GR0 = g_G[i0r] + g_G[i0r + P] + g_G[i0r + 2 * P];
    const float GI0 = g_G[i0i] + g_G[i0i + P] + g_G[i0i + 2 * P];
    const float GR1 = g_G[i1r] + g_G[i1r + P] + g_G[i1r + 2 * P];
    const float GI1 = g_G[i1i] + g_G[i1i + P] + g_G[i1i + 2 * P];
    const float q0r = Qsrc[(size_t)n0 * ldq + c], q0i = Qsrc[(size_t)n0 * ldq + c + 256];
    const float q1r = Qsrc[(size_t)n1 * ldq + c], q1i = Qsrc[(size_t)n1 * ldq + c + 256];
    const float x0r = h * q0r - h * GR0 + q0i;
    const float x0i = h * q0i - h * GI0 - q0r;
    const float x1r = h * q1r - h * GR1 + q1i;
    const float x1i = h * q1i - h * GI1 - q1r;
    g_XJ[i0r] = x0r; g_XJ[i0i] = x0i; g_XJ[i1r] = x1r; g_XJ[i1i] = x1i;
    g_Y[i0r] = x0r;  g_Y[i0i] = x0i;  g_Y[i1r] = x1r;  g_Y[i1i] = x1i;
    g_Bbf[(size_t)r * FB + c]       = packbf(x0r, x1r);
    g_Bbf[(size_t)r * FB + c + 256] = packbf(x0i, x1i);
}

// MODE 0: normal (write Y + Bbf(ny)).
// MODE 1: formQ-fused (write Q = P1 + ny, Bbf(Q); skip Y).
// MODE 2: last (write relu output directly; skip Y/Bbf).
template <int MODE>
__global__ void jacobi_kernel(const float* __restrict__ hp,
                              const float* __restrict__ dr, const float* __restrict__ di,
                              float* __restrict__ out) {
    const int i = blockIdx.x * 256 + threadIdx.x;
    const int r = i >> 8;
    const int c = i & 255;
    const int n0 = 2 * r, n1 = 2 * r + 1;
    const float h = *hp;
    const size_t P = (size_t)NN * FB;
    const size_t i0r = (size_t)n0 * FB + c, i0i = i0r + 256;
    const size_t i1r = (size_t)n1 * FB + c, i1i = i1r + 256;
    const float GR0 = g_G[i0r] + g_G[i0r + P] + g_G[i0r + 2 * P];
    const float GI0 = g_G[i0i] + g_G[i0i + P] + g_G[i0i + 2 * P];
    const float GR1 = g_G[i1r] + g_G[i1r + P] + g_G[i1r + 2 * P];
    const float GI1 = g_G[i1i] + g_G[i1i + P] + g_G[i1i + 2 * P];
    const float y0r = g_Y[i0r], y0i = g_Y[i0i];
    const float y1r = g_Y[i1r], y1i = g_Y[i1i];
    const float r0r = g_XJ[i0r] - (h * y0r - h * GR0 - y0i);
    const float r0i = g_XJ[i0i] - (h * y0i - h * GI0 + y0r);
    const float r1r = g_XJ[i1r] - (h * y1r - h * GR1 - y1i);
    const float r1i = g_XJ[i1i] - (h * y1i - h * GI1 + y1r);
    const float d0r = dr[n0], d0i = di[n0];
    const float d1r = dr[n1], d1i = di[n1];
    const float ny0r = y0r + d0r * r0r - d0i * r0i;
    const float ny0i = y0i + d0r * r0i + d0i * r0r;
    const float ny1r = y1r + d1r * r1r - d1i * r1i;
    const float ny1i = y1i + d1r * r1i + d1i * r1r;
    if (MODE == 2) {
        const float v0 = g_P[(size_t)n0 * NPACK + 1024 + c] + 2.f * ny0r;
        const float v1 = g_P[(size_t)n1 * NPACK + 1024 + c] + 2.f * ny1r;
        out[(size_t)n0 * FOUT + c] = v0 > 0.f ? v0 : 0.f;
        out[(size_t)n1 * FOUT + c] = v1 > 0.f ? v1 : 0.f;
    } else if (MODE == 1) {
        const float q0r = g_P[(size_t)n0 * NPACK + 512 + c] + ny0r;
        const float q0i = g_P[(size_t)n0 * NPACK + 768 + c] + ny0i;
        const float q1r = g_P[(size_t)n1 * NPACK + 512 + c] + ny1r;
        const float q1i = g_P[(size_t)n1 * NPACK + 768 + c] + ny1i;
        g_Q[i0r] = q0r; g_Q[i0i] = q0i; g_Q[i1r] = q1r; g_Q[i1i] = q1i;
        g_Bbf[(size_t)r * FB + c]       = packbf(q0r, q1r);
        g_Bbf[(size_t)r * FB + c + 256] = packbf(q0i, q1i);
    } else {
        g_Y[i0r] = ny0r; g_Y[i0i] = ny0i; g_Y[i1r] = ny1r; g_Y[i1i] = ny1i;
        g_Bbf[(size_t)r * FB + c]       = packbf(ny0r, ny1r);
        g_Bbf[(size_t)r * FB + c + 256] = packbf(ny0i, ny1i);
    }
}

// ---------------- orchestration --------------------------------------------------
#define SMEM_BIG   (4 * 4288 * 4)
#define SMEM_PROJ  (3 * 8576 * 4)

extern "C" void kernel_launch(void* const* d_in, const int* in_sizes, int n_in,
                              void* d_out, int out_size) {
    const float* x   = (const float*)d_in[0];
    const float* adj = (const float*)d_in[1];
    const float* hp  = (const float*)d_in[2];
    const float* w0  = (const float*)d_in[3];
    const float* wr  = (const float*)d_in[4];
    const float* wi  = (const float*)d_in[5];
    float* out = (float*)d_out;

    float *Pp, *Q, *G, *dr, *di;
    uint32_t *adjp, *Bbf, *xh, *xl, *wh, *wl;
    cudaGetSymbolAddress((void**)&Pp, g_P);
    cudaGetSymbolAddress((void**)&Q, g_Q);
    cudaGetSymbolAddress((void**)&G, g_G);
    cudaGetSymbolAddress((void**)&dr, g_dr);
    cudaGetSymbolAddress((void**)&di, g_di);
    cudaGetSymbolAddress((void**)&adjp, g_adjp);
    cudaGetSymbolAddress((void**)&Bbf, g_Bbf);
    cudaGetSymbolAddress((void**)&xh, g_xh);
    cudaGetSymbolAddress((void**)&xl, g_xl);
    cudaGetSymbolAddress((void**)&wh, g_wh);
    cudaGetSymbolAddress((void**)&wl, g_wl);

    cudaFuncSetAttribute(gemm_big,  cudaFuncAttributeMaxDynamicSharedMemorySize, SMEM_BIG);
    cudaFuncSetAttribute(gemm_proj, cudaFuncAttributeMaxDynamicSharedMemorySize, SMEM_PROJ);

    // merged prep: rowsum + packW(hi/lo) + packX + packAdj
    prep_kernel<<<9728, 256>>>(adj, hp, x, w0, wr, wi);

    // P = x @ WALL (split-bf16, fp32-grade); P2 cols also emit Bbf directly
    gemm_proj<<<dim3(10, 24, 1), 256, SMEM_PROJ>>>(xh, xl, wh, wl, Pp, Bbf);

    const dim3 gridBig(4, 24, 3);
    const size_t PL = (size_t)NN * FB;

    // applyK #1: Y = K @ P2 ; last jacobi fuses Q = P1 + Y
    gemm_big<<<gridBig, 256, SMEM_BIG>>>(adjp, Bbf, G, PL);
    xj_kernel<<<1536, 256>>>(hp, Pp, NPACK);
    gemm_big<<<gridBig, 256, SMEM_BIG>>>(adjp, Bbf, G, PL);
    jacobi_kernel<0><<<1536, 256>>>(hp, dr, di, out);
    gemm_big<<<gridBig, 256, SMEM_BIG>>>(adjp, Bbf, G, PL);
    jacobi_kernel<0><<<1536, 256>>>(hp, dr, di, out);
    gemm_big<<<gridBig, 256, SMEM_BIG>>>(adjp, Bbf, G, PL);
    jacobi_kernel<1><<<1536, 256>>>(hp, dr, di, out);   // formQ fused

    // applyK #2: Y = K @ Q ; last jacobi fuses relu
    gemm_big<<<gridBig, 256, SMEM_BIG>>>(adjp, Bbf, G, PL);
    xj_kernel<<<1536, 256>>>(hp, Q, FB);
    gemm_big<<<gridBig, 256, SMEM_BIG>>>(adjp, Bbf, G, PL);
    jacobi_kernel<0><<<1536, 256>>>(hp, dr, di, out);
    gemm_big<<<gridBig, 256, SMEM_BIG>>>(adjp, Bbf, G, PL);
    jacobi_kernel<0><<<1536, 256>>>(hp, dr, di, out);
    gemm_big<<<gridBig, 256, SMEM_BIG>>>(adjp, Bbf, G, PL);
    jacobi_kernel<2><<<1536, 256>>>(hp, dr, di, out);   // relu fused
}

// round 12
// speedup vs baseline: 1.3184x; 1.0388x over previous
#include <cuda_runtime.h>
#include <cstdint>
#include <cstddef>

#define NN 3072
#define FB 512     // working block width (256 complex -> 512 real cols)
#define FOUT 256
#define FIN 512
#define NPACK 1280 // [wr1|wi1 | wr0|wi0 | w0]

// ---------------- scratch (device globals) -------------------------------------
__device__ __align__(1024) uint32_t g_adjp[(size_t)NN * NN / 2]; // bf16 fragment-tiled adj
__device__ __align__(1024) uint32_t g_Bbf[(NN / 2) * FB];        // bf16x2 interleaved B operand
__device__ __align__(1024) uint32_t g_xh[(size_t)NN * FIN / 2];  // x fragment-tiled bf16 hi
__device__ __align__(1024) uint32_t g_xl[(size_t)NN * FIN / 2];  // x fragment-tiled bf16 lo
__device__ __align__(1024) uint32_t g_wh[(FIN / 2) * NPACK];     // W pair-rows bf16 hi
__device__ __align__(1024) uint32_t g_wl[(FIN / 2) * NPACK];     // W pair-rows bf16 lo
__device__ __align__(128) float g_P[NN * NPACK];                 // packed projections
__device__ __align__(128) float g_Q[NN * FB];
__device__ __align__(128) float g_Y[NN * FB];
__device__ __align__(128) float g_XJ[NN * FB];
__device__ __align__(128) float g_G[3 * NN * FB];                // split-K partials
__device__ __align__(128) float g_dr[NN];
__device__ __align__(128) float g_di[NN];

// ---------------- helpers -------------------------------------------------------
__device__ __forceinline__ uint32_t packbf(float lo, float hi) {
    uint32_t d;
    asm("cvt.rn.bf16x2.f32 %0, %1, %2;" : "=r"(d) : "f"(hi), "f"(lo));
    return d;
}
__device__ __forceinline__ uint32_t packres(float lo, float hi, uint32_t h) {
    const float hl = __uint_as_float(h << 16);
    const float hh = __uint_as_float(h & 0xFFFF0000u);
    return packbf(lo - hl, hi - hh);
}
__device__ __forceinline__ uint32_t smem_u32(const void* p) {
    uint32_t a;
    asm("{ .reg .u64 t; cvta.to.shared.u64 t, %1; cvt.u32.u64 %0, t; }" : "=r"(a) : "l"(p));
    return a;
}
__device__ __forceinline__ void cpasync16(uint32_t dst, const void* src) {
    asm volatile("cp.async.cg.shared.global [%0], [%1], 16;" :: "r"(dst), "l"(src) : "memory");
}
__device__ __forceinline__ void mma16(float c[4],
                                      uint32_t a0, uint32_t a1, uint32_t a2, uint32_t a3,
                                      uint32_t b0, uint32_t b1) {
    asm volatile(
        "mma.sync.aligned.m16n8k16.row.col.f32.bf16.bf16.f32 "
        "{%0,%1,%2,%3}, {%4,%5,%6,%7}, {%8,%9}, {%0,%1,%2,%3};"
        : "+f"(c[0]), "+f"(c[1]), "+f"(c[2]), "+f"(c[3])
        : "r"(a0), "r"(a1), "r"(a2), "r"(a3), "r"(b0), "r"(b1));
}

// ================= BIG GEMM: bf16-resident, cp.async 3-stage, BK=64 =============
// G[z] = adj[:, zslice] @ Ybf[zslice, :]   (fp32 out, 128x128 CTA, 256 thr)
// Stage (u32): A 4 k16-tiles (4x1056 = 4224) + B 32 pair-rows x 136 = 4352 -> 8576
__global__ void __launch_bounds__(256, 2)
gemm_big(const uint32_t* __restrict__ Ap, const uint32_t* __restrict__ Bbf,
         float* __restrict__ C, size_t cPlane) {
    constexpr int STAGE = 8576;
    extern __shared__ __align__(16) uint32_t sm[];
    const uint32_t smb = smem_u32(sm);

    const int tid  = threadIdx.x;
    const int lane = tid & 31;
    const int warp = tid >> 5;
    const int wrow = warp >> 2;
    const int wcol = warp & 3;
    const int g    = lane >> 2;
    const int t    = lane & 3;
    const int bMt  = blockIdx.y;
    const int bN   = blockIdx.x * 128;
    const int kt0  = blockIdx.z * 64;   // k16-tile base (64 k16 per z-slice)

    float acc[4][4][4];
#pragma unroll
    for (int i = 0; i < 4; i++)
#pragma unroll
        for (int j = 0; j < 4; j++)
#pragma unroll
            for (int k = 0; k < 4; k++) acc[i][j][k] = 0.f;

    auto issueStage = [&](int st, int s) {
        const uint32_t stb = smb + st * (STAGE * 4);
        const int kt16 = kt0 + s * 4;
        const size_t atile = ((size_t)bMt * 192 + kt16) * 1024;
#pragma unroll
        for (int i = 0; i < 4; i++) {
            const int c = tid + i * 256;          // 0..1023
            const int j = c >> 8, w = c & 255;
            cpasync16(stb + (uint32_t)(j * 1056 + (w >> 6) * 264 + (w & 63) * 4) * 4,
                      Ap + atile + c * 4);
        }
        const size_t brow = (size_t)kt16 * 8 * FB + bN;
#pragma unroll
        for (int i = 0; i < 4; i++) {
            const int c = tid + i * 256;          // 0..1023
            const int row = c >> 5, c4 = (c & 31) * 4;
            cpasync16(stb + 16896 + (uint32_t)(row * 136 + c4) * 4,
                      Bbf + brow + (size_t)row * FB + c4);
        }
        asm volatile("cp.async.commit_group;" ::: "memory");
    };

    const int nT = 16;   // 1024 k / 64
    issueStage(0, 0);
    issueStage(1, 1);

    for (int s = 0; s < nT; s++) {
        const int st = s % 3;
        if (s + 1 < nT) asm volatile("cp.async.wait_group 1;" ::: "memory");
        else            asm volatile("cp.async.wait_group 0;" ::: "memory");
        __syncthreads();
        // safe: buffer (s+2)%3 was last read at iter s-1, complete before barrier
        if (s + 2 < nT) issueStage((s + 2) % 3, s + 2);

        const uint32_t* Abase = sm + st * STAGE + t * 264;
        const uint32_t* Bbase = sm + st * STAGE + 4224;
#pragma unroll
        for (int ks = 0; ks < 4; ks++) {
            uint4 afv[4];
            uint32_t bf[4][2];
#pragma unroll
            for (int mti = 0; mti < 4; mti++)
                afv[mti] = *(const uint4*)(Abase + ks * 1056 + ((wrow * 4 + mti) * 8 + g) * 4);
#pragma unroll
            for (int nt = 0; nt < 4; nt++) {
                const int n0 = wcol * 32 + nt * 8 + g;
                bf[nt][0] = Bbase[(ks * 8 + t) * 136 + n0];
                bf[nt][1] = Bbase[(ks * 8 + t + 4) * 136 + n0];
            }
#pragma unroll
            for (int mti = 0; mti < 4; mti++)
#pragma unroll
                for (int nt = 0; nt < 4; nt++)
                    mma16(acc[mti][nt], afv[mti].x, afv[mti].y, afv[mti].z, afv[mti].w,
                          bf[nt][0], bf[nt][1]);
        }
    }

    float* Ct = C + blockIdx.z * cPlane;
#pragma unroll
    for (int mti = 0; mti < 4; mti++) {
        const int row = bMt * 128 + wrow * 64 + mti * 16 + g;
#pragma unroll
        for (int nt = 0; nt < 4; nt++) {
            const int col = bN + wcol * 32 + nt * 8 + 2 * t;
            float* p = Ct + (size_t)row * FB + col;
            p[0]                  = acc[mti][nt][0];
            p[1]                  = acc[mti][nt][1];
            p[(size_t)8 * FB]     = acc[mti][nt][2];
            p[(size_t)8 * FB + 1] = acc[mti][nt][3];
        }
    }
}

// ================= projection GEMM (split-bf16, 3-stage) + fused packP2 ==========
__global__ void __launch_bounds__(256, 2)
gemm_proj(const uint32_t* __restrict__ Ah, const uint32_t* __restrict__ Al,
          const uint32_t* __restrict__ Bh, const uint32_t* __restrict__ Bl,
          float* __restrict__ C, uint32_t* __restrict__ Bout) {
    constexpr int AU = 2112;
    constexpr int BOFF = 4224;
    constexpr int BU = 16 * 136;
    constexpr int STAGE = BOFF + 2 * BU;   // 8576 u32

    extern __shared__ __align__(16) uint32_t sm[];
    const uint32_t smb = smem_u32(sm);

    const int tid  = threadIdx.x;
    const int lane = tid & 31;
    const int warp = tid >> 5;
    const int wrow = warp >> 2;
    const int wcol = warp & 3;
    const int g    = lane >> 2;
    const int t    = lane & 3;
    const int bMt  = blockIdx.y;
    const int bN   = blockIdx.x * 128;

    float acc[4][4][4];
#pragma unroll
    for (int i = 0; i < 4; i++)
#pragma unroll
        for (int j = 0; j < 4; j++)
#pragma unroll
            for (int k = 0; k < 4; k++) acc[i][j][k] = 0.f;

    auto issueStage = [&](int st, int s) {
        const uint32_t stb = smb + st * (STAGE * 4);
        const int kt16 = s * 2;
        const size_t atile = ((size_t)bMt * 32 + kt16) * 1024;
#pragma unroll
        for (int i = 0; i < 2; i++) {
            const int c = tid + i * 256;
            const int j = c >> 8, w = c & 255;
            const uint32_t off = (uint32_t)(j * 1056 + (w >> 6) * 264 + (w & 63) * 4) * 4;
            cpasync16(stb + off, Ah + atile + c * 4);
            cpasync16(stb + AU * 4 + off, Al + atile + c * 4);
        }
        const size_t brow = (size_t)kt16 * 8 * NPACK + bN;
#pragma unroll
        for (int i = 0; i < 2; i++) {
            const int c = tid + i * 256;
            const int row = c >> 5, c4 = (c & 31) * 4;
            const uint32_t off = (uint32_t)(row * 136 + c4) * 4;
            cpasync16(stb + BOFF * 4 + off, Bh + brow + (size_t)row * NPACK + c4);
            cpasync16(stb + (BOFF + BU) * 4 + off, Bl + brow + (size_t)row * NPACK + c4);
        }
        asm volatile("cp.async.commit_group;" ::: "memory");
    };

    const int nT = 16;
    issueStage(0, 0);
    issueStage(1, 1);

    for (int s = 0; s < nT; s++) {
        const int st = s % 3;
        if (s + 1 < nT) asm volatile("cp.async.wait_group 1;" ::: "memory");
        else            asm volatile("cp.async.wait_group 0;" ::: "memory");
        __syncthreads();
        if (s + 2 < nT) issueStage((s + 2) % 3, s + 2);

        const uint32_t* Sb = sm + st * STAGE;
        const uint32_t* Abase = Sb + t * 264;
        const uint32_t* Bbase = Sb + BOFF;
#pragma unroll
        for (int ks = 0; ks < 2; ks++) {
            uint4 afh[4], afl[4];
            uint32_t bfh[4][2], bfl[4][2];
#pragma unroll
            for (int mti = 0; mti < 4; mti++) {
                afh[mti] = *(const uint4*)(Abase + ks * 1056 + ((wrow * 4 + mti) * 8 + g) * 4);
                afl[mti] = *(const uint4*)(Abase + AU + ks * 1056 + ((wrow * 4 + mti) * 8 + g) * 4);
            }
#pragma unroll
            for (int nt = 0; nt < 4; nt++) {
                const int n0 = wcol * 32 + nt * 8 + g;
                bfh[nt][0] = Bbase[(ks * 8 + t) * 136 + n0];
                bfh[nt][1] = Bbase[(ks * 8 + t + 4) * 136 + n0];
                bfl[nt][0] = Bbase[BU + (ks * 8 + t) * 136 + n0];
                bfl[nt][1] = Bbase[BU + (ks * 8 + t + 4) * 136 + n0];
            }
#pragma unroll
            for (int mti = 0; mti < 4; mti++)
#pragma unroll
                for (int nt = 0; nt < 4; nt++) {
                    mma16(acc[mti][nt], afh[mti].x, afh[mti].y, afh[mti].z, afh[mti].w,
                          bfl[nt][0], bfl[nt][1]);
                    mma16(acc[mti][nt], afl[mti].x, afl[mti].y, afl[mti].z, afl[mti].w,
                          bfh[nt][0], bfh[nt][1]);
                    mma16(acc[mti][nt], afh[mti].x, afh[mti].y, afh[mti].z, afh[mti].w,
                          bfh[nt][0], bfh[nt][1]);
                }
        }
    }

#pragma unroll
    for (int mti = 0; mti < 4; mti++) {
        const int row = bMt * 128 + wrow * 64 + mti * 16 + g;
#pragma unroll
        for (int nt = 0; nt < 4; nt++) {
            const int col = bN + wcol * 32 + nt * 8 + 2 * t;
            float* p = C + (size_t)row * NPACK + col;
            p[0]                     = acc[mti][nt][0];
            p[1]                     = acc[mti][nt][1];
            p[(size_t)8 * NPACK]     = acc[mti][nt][2];
            p[(size_t)8 * NPACK + 1] = acc[mti][nt][3];
        }
    }

    if (blockIdx.x < 4) {
#pragma unroll
        for (int mti = 0; mti < 4; mti++) {
            const int row = bMt * 128 + wrow * 64 + mti * 16 + g;
#pragma unroll
            for (int nt = 0; nt < 4; nt++) {
                const int col = bN + wcol * 32 + nt * 8 + 2 * t;
                const float v00 = acc[mti][nt][0], v01 = acc[mti][nt][1];
                const float v10 = acc[mti][nt][2], v11 = acc[mti][nt][3];
                const float o00 = __shfl_xor_sync(0xffffffffu, v00, 4);
                const float o01 = __shfl_xor_sync(0xffffffffu, v01, 4);
                const float o10 = __shfl_xor_sync(0xffffffffu, v10, 4);
                const float o11 = __shfl_xor_sync(0xffffffffu, v11, 4);
                if (!(g & 1)) {
                    *(uint2*)&Bout[(size_t)(row >> 1) * FB + col] =
                        make_uint2(packbf(v00, o00), packbf(v01, o01));
                    *(uint2*)&Bout[(size_t)((row + 8) >> 1) * FB + col] =
                        make_uint2(packbf(v10, o10), packbf(v11, o11));
                }
            }
        }
    }
}

// ---------------- merged prep kernel ----------------------------------------------
__device__ __forceinline__ float wallVal(const float* __restrict__ w0,
                                         const float* __restrict__ wr,
                                         const float* __restrict__ wi, int r, int c) {
    if (c < 256)       return wr[(size_t)FIN * FOUT + (size_t)r * FOUT + c];
    if (c < 512)       return wi[(size_t)FIN * FOUT + (size_t)r * FOUT + (c - 256)];
    if (c < 768)       return wr[(size_t)r * FOUT + (c - 512)];
    if (c < 1024)      return wi[(size_t)r * FOUT + (c - 768)];
    return w0[(size_t)r * FOUT + (c - 1024)];
}

__device__ __forceinline__ void packFragRow(const float* __restrict__ src, int K,
                                            uint32_t* __restrict__ dsth,
                                            uint32_t* __restrict__ dstl,
                                            int ktiles, int kt, int mt, int tp) {
    const int mloc = tp >> 1, half = tp & 1;
    const float* s = src + (size_t)(mt * 128 + mloc) * K + kt * 16 + half * 8;
    const float4 v0 = *(const float4*)s;
    const float4 v1 = *(const float4*)(s + 4);
    const float v[8] = {v0.x, v0.y, v0.z, v0.w, v1.x, v1.y, v1.z, v1.w};
    const int mg   = (mloc & 7) | ((mloc >> 4) << 3);
    const int msel = (mloc >> 3) & 1;
    const int reg  = half * 2 + msel;
    const size_t base = ((size_t)mt * ktiles + kt) * 1024 + mg * 4 + reg;
#pragma unroll
    for (int tt = 0; tt < 4; tt++) {
        const uint32_t h = packbf(v[2 * tt], v[2 * tt + 1]);
        dsth[base + tt * 256] = h;
        if (dstl) dstl[base + tt * 256] = packres(v[2 * tt], v[2 * tt + 1], h);
    }
}

__global__ void prep_kernel(const float* __restrict__ adj, const float* __restrict__ hp,
                            const float* __restrict__ x,
                            const float* __restrict__ w0, const float* __restrict__ wr,
                            const float* __restrict__ wi) {
    const int b = blockIdx.x;
    if (b < 3072) {
        __shared__ float sh[256];
        const float* a = adj + (size_t)b * NN;
        float s = 0.f;
        for (int c = threadIdx.x; c < NN; c += 256) s += a[c];
        sh[threadIdx.x] = s;
        __syncthreads();
        for (int o = 128; o > 0; o >>= 1) {
            if (threadIdx.x < o) sh[threadIdx.x] += sh[threadIdx.x + o];
            __syncthreads();
        }
        if (threadIdx.x == 0) {
            const float h = *hp;
            const float sv = h * (1.0f - sh[0]);
            const float inv = 1.0f / (sv * sv + 1.0f);
            g_dr[b] = sv * inv;
            g_di[b] = -inv;
        }
    } else if (b < 4352) {
        const int i = (b - 3072) * 256 + threadIdx.x;
        const int r = i / NPACK;
        const int c = i % NPACK;
        const float v0 = wallVal(w0, wr, wi, 2 * r, c);
        const float v1 = wallVal(w0, wr, wi, 2 * r + 1, c);
        const uint32_t h = packbf(v0, v1);
        g_wh[i] = h;
        g_wl[i] = packres(v0, v1, h);
    } else if (b < 5120) {
        const int p = b - 4352;
        packFragRow(x, FIN, g_xh, g_xl, 32, p & 31, p >> 5, threadIdx.x);
    } else {
        const int p = b - 5120;
        packFragRow(adj, NN, g_adjp, nullptr, 192, p % 192, p / 192, threadIdx.x);
    }
}

// ---------------- elementwise kernels --------------------------------------------

// xj: XJ = (hL - iI)@Qsrc ; Bbf = bf16(XJ). Y is NOT written (first jacobi uses XJ).
__global__ void xj_kernel(const float* __restrict__ hp,
                          const float* __restrict__ Qsrc, int ldq) {
    const int i = blockIdx.x * 256 + threadIdx.x;   // over 1536*256
    const int r = i >> 8;
    const int c = i & 255;
    const int n0 = 2 * r, n1 = 2 * r + 1;
    const float h = *hp;
    const size_t P = (size_t)NN * FB;
    const size_t i0r = (size_t)n0 * FB + c, i0i = i0r + 256;
    const size_t i1r = (size_t)n1 * FB + c, i1i = i1r + 256;
    const float GR0 = g_G[i0r] + g_G[i0r + P] + g_G[i0r + 2 * P];
    const float GI0 = g_G[i0i] + g_G[i0i + P] + g_G[i0i + 2 * P];
    const float GR1 = g_G[i1r] + g_G[i1r + P] + g_G[i1r + 2 * P];
    const float GI1 = g_G[i1i] + g_G[i1i + P] + g_G[i1i + 2 * P];
    const float q0r = Qsrc[(size_t)n0 * ldq + c], q0i = Qsrc[(size_t)n0 * ldq + c + 256];
    const float q1r = Qsrc[(size_t)n1 * ldq + c], q1i = Qsrc[(size_t)n1 * ldq + c + 256];
    const float x0r = h * q0r - h * GR0 + q0i;
    const float x0i = h * q0i - h * GI0 - q0r;
    const float x1r = h * q1r - h * GR1 + q1i;
    const float x1i = h * q1i - h * GI1 - q1r;
    g_XJ[i0r] = x0r; g_XJ[i0i] = x0i; g_XJ[i1r] = x1r; g_XJ[i1i] = x1i;
    g_Bbf[(size_t)r * FB + c]       = packbf(x0r, x1r);
    g_Bbf[(size_t)r * FB + c + 256] = packbf(x0i, x1i);
}

// MODE 0: normal (write Y + Bbf(ny)).
// MODE 1: formQ-fused (write Q = P1 + ny, Bbf(Q); skip Y).
// MODE 2: last (write relu output directly; skip Y/Bbf).
// FIRST 1: Y is implicitly XJ (skip Y read).
template <int MODE, int FIRST>
__global__ void jacobi_kernel(const float* __restrict__ hp,
                              const float* __restrict__ dr, const float* __restrict__ di,
                              float* __restrict__ out) {
    const int i = blockIdx.x * 256 + threadIdx.x;
    const int r = i >> 8;
    const int c = i & 255;
    const int n0 = 2 * r, n1 = 2 * r + 1;
    const float h = *hp;
    const size_t P = (size_t)NN * FB;
    const size_t i0r = (size_t)n0 * FB + c, i0i = i0r + 256;
    const size_t i1r = (size_t)n1 * FB + c, i1i = i1r + 256;
    const float GR0 = g_G[i0r] + g_G[i0r + P] + g_G[i0r + 2 * P];
    const float GI0 = g_G[i0i] + g_G[i0i + P] + g_G[i0i + 2 * P];
    const float GR1 = g_G[i1r] + g_G[i1r + P] + g_G[i1r + 2 * P];
    const float GI1 = g_G[i1i] + g_G[i1i + P] + g_G[i1i + 2 * P];
    const float x0r = g_XJ[i0r], x0i = g_XJ[i0i];
    const float x1r = g_XJ[i1r], x1i = g_XJ[i1i];
    const float y0r = FIRST ? x0r : g_Y[i0r], y0i = FIRST ? x0i : g_Y[i0i];
    const float y1r = FIRST ? x1r : g_Y[i1r], y1i = FIRST ? x1i : g_Y[i1i];
    const float r0r = x0r - (h * y0r - h * GR0 - y0i);
    const float r0i = x0i - (h * y0i - h * GI0 + y0r);
    const float r1r = x1r - (h * y1r - h * GR1 - y1i);
    const float r1i = x1i - (h * y1i - h * GI1 + y1r);
    const float d0r = dr[n0], d0i = di[n0];
    const float d1r = dr[n1], d1i = di[n1];
    const float ny0r = y0r + d0r * r0r - d0i * r0i;
    const float ny0i = y0i + d0r * r0i + d0i * r0r;
    const float ny1r = y1r + d1r * r1r - d1i * r1i;
    const float ny1i = y1i + d1r * r1i + d1i * r1r;
    if (MODE == 2) {
        const float v0 = g_P[(size_t)n0 * NPACK + 1024 + c] + 2.f * ny0r;
        const float v1 = g_P[(size_t)n1 * NPACK + 1024 + c] + 2.f * ny1r;
        out[(size_t)n0 * FOUT + c] = v0 > 0.f ? v0 : 0.f;
        out[(size_t)n1 * FOUT + c] = v1 > 0.f ? v1 : 0.f;
    } else if (MODE == 1) {
        const float q0r = g_P[(size_t)n0 * NPACK + 512 + c] + ny0r;
        const float q0i = g_P[(size_t)n0 * NPACK + 768 + c] + ny0i;
        const float q1r = g_P[(size_t)n1 * NPACK + 512 + c] + ny1r;
        const float q1i = g_P[(size_t)n1 * NPACK + 768 + c] + ny1i;
        g_Q[i0r] = q0r; g_Q[i0i] = q0i; g_Q[i1r] = q1r; g_Q[i1i] = q1i;
        g_Bbf[(size_t)r * FB + c]       = packbf(q0r, q1r);
        g_Bbf[(size_t)r * FB + c + 256] = packbf(q0i, q1i);
    } else {
        g_Y[i0r] = ny0r; g_Y[i0i] = ny0i; g_Y[i1r] = ny1r; g_Y[i1i] = ny1i;
        g_Bbf[(size_t)r * FB + c]       = packbf(ny0r, ny1r);
        g_Bbf[(size_t)r * FB + c + 256] = packbf(ny0i, ny1i);
    }
}

// ---------------- orchestration --------------------------------------------------
#define SMEM_BIG   (3 * 8576 * 4)
#define SMEM_PROJ  (3 * 8576 * 4)

extern "C" void kernel_launch(void* const* d_in, const int* in_sizes, int n_in,
                              void* d_out, int out_size) {
    const float* x   = (const float*)d_in[0];
    const float* adj = (const float*)d_in[1];
    const float* hp  = (const float*)d_in[2];
    const float* w0  = (const float*)d_in[3];
    const float* wr  = (const float*)d_in[4];
    const float* wi  = (const float*)d_in[5];
    float* out = (float*)d_out;

    float *Pp, *Q, *G, *dr, *di;
    uint32_t *adjp, *Bbf, *xh, *xl, *wh, *wl;
    cudaGetSymbolAddress((void**)&Pp, g_P);
    cudaGetSymbolAddress((void**)&Q, g_Q);
    cudaGetSymbolAddress((void**)&G, g_G);
    cudaGetSymbolAddress((void**)&dr, g_dr);
    cudaGetSymbolAddress((void**)&di, g_di);
    cudaGetSymbolAddress((void**)&adjp, g_adjp);
    cudaGetSymbolAddress((void**)&Bbf, g_Bbf);
    cudaGetSymbolAddress((void**)&xh, g_xh);
    cudaGetSymbolAddress((void**)&xl, g_xl);
    cudaGetSymbolAddress((void**)&wh, g_wh);
    cudaGetSymbolAddress((void**)&wl, g_wl);

    cudaFuncSetAttribute(gemm_big,  cudaFuncAttributeMaxDynamicSharedMemorySize, SMEM_BIG);
    cudaFuncSetAttribute(gemm_proj, cudaFuncAttributeMaxDynamicSharedMemorySize, SMEM_PROJ);

    // merged prep: rowsum + packW(hi/lo) + packX + packAdj
    prep_kernel<<<9728, 256>>>(adj, hp, x, w0, wr, wi);

    // P = x @ WALL (split-bf16, fp32-grade); P2 cols also emit Bbf directly
    gemm_proj<<<dim3(10, 24, 1), 256, SMEM_PROJ>>>(xh, xl, wh, wl, Pp, Bbf);

    const dim3 gridBig(4, 24, 3);
    const size_t PL = (size_t)NN * FB;

    // applyK #1: Y = K @ P2 ; last jacobi fuses Q = P1 + Y
    gemm_big<<<gridBig, 256, SMEM_BIG>>>(adjp, Bbf, G, PL);
    xj_kernel<<<1536, 256>>>(hp, Pp, NPACK);
    gemm_big<<<gridBig, 256, SMEM_BIG>>>(adjp, Bbf, G, PL);
    jacobi_kernel<0, 1><<<1536, 256>>>(hp, dr, di, out);
    gemm_big<<<gridBig, 256, SMEM_BIG>>>(adjp, Bbf, G, PL);
    jacobi_kernel<0, 0><<<1536, 256>>>(hp, dr, di, out);
    gemm_big<<<gridBig, 256, SMEM_BIG>>>(adjp, Bbf, G, PL);
    jacobi_kernel<1, 0><<<1536, 256>>>(hp, dr, di, out);   // formQ fused

    // applyK #2: Y = K @ Q ; last jacobi fuses relu
    gemm_big<<<gridBig, 256, SMEM_BIG>>>(adjp, Bbf, G, PL);
    xj_kernel<<<1536, 256>>>(hp, Q, FB);
    gemm_big<<<gridBig, 256, SMEM_BIG>>>(adjp, Bbf, G, PL);
    jacobi_kernel<0, 1><<<1536, 256>>>(hp, dr, di, out);
    gemm_big<<<gridBig, 256, SMEM_BIG>>>(adjp, Bbf, G, PL);
    jacobi_kernel<0, 0><<<1536, 256>>>(hp, dr, di, out);
    gemm_big<<<gridBig, 256, SMEM_BIG>>>(adjp, Bbf, G, PL);
    jacobi_kernel<2, 0><<<1536, 256>>>(hp, dr, di, out);   // relu fused
}